// round 5
// baseline (speedup 1.0000x reference)
#include <cuda_runtime.h>
#include <math.h>

#define NTAPS 201
#define HALF  100
#define NT2   203          // extended tap loop (covers shifted-weight tails)
#define TILE  256
#define WIN   (TILE + 208)

typedef unsigned long long ull;

__device__ __forceinline__ ull pk(float lo, float hi) {
    ull r; asm("mov.b64 %0, {%1, %2};" : "=l"(r) : "f"(lo), "f"(hi)); return r;
}
__device__ __forceinline__ float2 upk(ull v) {
    float2 r; asm("mov.b64 {%0, %1}, %2;" : "=f"(r.x), "=f"(r.y) : "l"(v)); return r;
}
__device__ __forceinline__ void fma2(ull &d, ull a, ull b) {
    asm("fma.rn.f32x2 %0, %1, %2, %0;" : "+l"(d) : "l"(a), "l"(b));
}
__device__ __forceinline__ ull fma2r(ull a, ull b, ull c) {
    ull r; asm("fma.rn.f32x2 %0, %1, %2, %3;" : "=l"(r) : "l"(a), "l"(b), "l"(c)); return r;
}
__device__ __forceinline__ ull mul2(ull a, ull b) {
    ull r; asm("mul.rn.f32x2 %0, %1, %2;" : "=l"(r) : "l"(a), "l"(b)); return r;
}

// Shared layouts:
//  sU[idx]      = { (r0,i0), (r1,i1) }          natural pairs (u_m)
//  sV[idx]      = { (i0,-r0), (i1,-r1) }        rotated pairs (v_m)
//  sW[5j+0..4]  = { wrP1s|wiP1s, wrP2s|wiP2s, wrM1s|wiM1s, wrM2s|wiM2s, (wx,wq)|unused }
// Splats of each position are built in registers from sU and ring-rotated
// for the +1/+2 shift products.

__global__ __launch_bounds__(TILE, 2)
void snse_kernel(const float* __restrict__ x_real,
                 const float* __restrict__ x_imag,
                 const float* __restrict__ task_info,
                 const float* __restrict__ C00p,
                 const float* __restrict__ ixpm_w,
                 const float* __restrict__ icixpm_w,
                 const float* __restrict__ fwm_wr,
                 const float* __restrict__ fwm_wi,
                 float* __restrict__ out,
                 int M, int Lout)
{
    __shared__ ulonglong2 sU[WIN];
    __shared__ ulonglong2 sV[WIN];
    __shared__ ulonglong2 sW[NT2 * 5];

    const int b  = blockIdx.y;
    const int l0 = blockIdx.x * TILE;
    const int t  = threadIdx.x;

    const float dbm = task_info[b * 4];
    const float P   = exp10f(dbm * 0.1f) * 0.5f;   // /Nm, Nm=2
    const float sP  = sqrtf(P);
    const float rsP = 1.0f / sP;
    const float C00 = C00p[0];

    // ---- build pre-splatted weight table ----
    for (int j = t; j < NT2; j += TILE) {
        float wrP1 = (j <= 200) ? fwm_wr[2 * NTAPS + j] : 0.f;
        float wiP1 = (j <= 200) ? fwm_wi[2 * NTAPS + j] : 0.f;
        float wrP2 = (j <= 200) ? fwm_wr[3 * NTAPS + j] : 0.f;
        float wiP2 = (j <= 200) ? fwm_wi[3 * NTAPS + j] : 0.f;
        float wrM1 = (j >= 1 && j <= 201) ? fwm_wr[1 * NTAPS + (j - 1)] : 0.f;
        float wiM1 = (j >= 1 && j <= 201) ? fwm_wi[1 * NTAPS + (j - 1)] : 0.f;
        float wrM2 = (j >= 2) ? fwm_wr[0 * NTAPS + (j - 2)] : 0.f;
        float wiM2 = (j >= 2) ? fwm_wi[0 * NTAPS + (j - 2)] : 0.f;
        float wx   = (j <= 200) ? ixpm_w[j]   : 0.f;
        float wq   = (j <= 200) ? icixpm_w[j] : 0.f;
        sW[5 * j + 0] = make_ulonglong2(pk(wrP1, wrP1), pk(wiP1, wiP1));
        sW[5 * j + 1] = make_ulonglong2(pk(wrP2, wrP2), pk(wiP2, wiP2));
        sW[5 * j + 2] = make_ulonglong2(pk(wrM1, wrM1), pk(wiM1, wiM1));
        sW[5 * j + 3] = make_ulonglong2(pk(wrM2, wrM2), pk(wiM2, wiM2));
        sW[5 * j + 4] = make_ulonglong2(pk(wx, wq), pk(wq, wq));
    }

    // ---- load scaled x window with mod-M wrap ----
    const float* xr = x_real + (size_t)b * M * 2;
    const float* xi = x_imag + (size_t)b * M * 2;
    for (int idx = t; idx < WIN; idx += TILE) {
        int g  = l0 - 2 + idx;
        int gm = (g < 0) ? g + M : ((g >= M) ? g - M : g);
        float r0 = xr[gm * 2 + 0] * sP, r1 = xr[gm * 2 + 1] * sP;
        float i0 = xi[gm * 2 + 0] * sP, i1 = xi[gm * 2 + 1] * sP;
        sU[idx] = make_ulonglong2(pk(r0, i0), pk(r1, i1));
        sV[idx] = make_ulonglong2(pk(i0, -r0), pk(i1, -r1));
    }
    __syncthreads();

    const int l = l0 + t;

    // ---- accumulators (f32x2 pairs) ----
    ull Ap[8], Bp[8], Am[8], Bm[8];
#pragma unroll
    for (int k = 0; k < 8; ++k) { Ap[k] = Bp[k] = Am[k] = Bm[k] = 0ULL; }
    float axp0 = 0.f, axp1 = 0.f;   // ixpm (scalar)
    ull qc  = 0ULL;                 // (qcr, qci)

    // splat rings (registers): cs2 = splats of p-2, cs1 = splats of p-1
    ull cs2r0, cs2i0, cs2r1, cs2i1;
    ull cs1r0, cs1i0, cs1r1, cs1i1;
    {
        ulonglong2 u0 = sU[t + 0];
        float2 a = upk(u0.x), c = upk(u0.y);
        cs2r0 = pk(a.x, a.x); cs2i0 = pk(a.y, a.y);
        cs2r1 = pk(c.x, c.x); cs2i1 = pk(c.y, c.y);
        ulonglong2 u1 = sU[t + 1];
        float2 d = upk(u1.x), e = upk(u1.y);
        cs1r0 = pk(d.x, d.x); cs1i0 = pk(d.y, d.y);
        cs1r1 = pk(e.x, e.x); cs1i1 = pk(e.y, e.y);
    }

#pragma unroll 2
    for (int j = 0; j < NT2; ++j) {
        const int iw = t + 2 + j;
        ulonglong2 uu  = sU[iw];           // u0,u1 at position p
        ulonglong2 vv  = sV[iw];           // v0,v1
        ulonglong2 wA  = sW[5 * j + 0];
        ulonglong2 wB  = sW[5 * j + 1];
        ulonglong2 wC  = sW[5 * j + 2];
        ulonglong2 wD  = sW[5 * j + 3];
        ulonglong2 wE  = sW[5 * j + 4];

        float2 f0 = upk(uu.x);
        float2 f1 = upk(uu.y);
        float2 wxq = upk(wE.x);            // (wx, wq) scalars
        // splats of p (register packs)
        ull nsr0 = pk(f0.x, f0.x), nsi0 = pk(f0.y, f0.y);
        ull nsr1 = pk(f1.x, f1.x), nsi1 = pk(f1.y, f1.y);

        // ---- ixpm (powers, scalar accumulate) ----
        float p0 = f0.x * f0.x + f0.y * f0.y;
        float p1 = f1.x * f1.x + f1.y * f1.y;
        axp0 += wxq.x * (2.f * p0 + p1);
        axp1 += wxq.x * (2.f * p1 + p0);

        // ---- icixpm product: q0 = X0[p]*conj(X1[p]) ----
        ull qd = fma2r(vv.x, nsi1, mul2(uu.x, nsr1));
        fma2(qc, qd, wE.y);

        // ---- shift +1 products (c = p-1 splats) ----
        {
            ull d;
            d = fma2r(vv.x, cs1i0, mul2(uu.x, cs1r0));   // D00
            fma2(Ap[0], d, wA.x); fma2(Bp[0], d, wA.y);
            fma2(Am[0], d, wC.x); fma2(Bm[0], d, wC.y);
            d = fma2r(vv.x, cs1i1, mul2(uu.x, cs1r1));   // D01
            fma2(Ap[1], d, wA.x); fma2(Bp[1], d, wA.y);
            fma2(Am[1], d, wC.x); fma2(Bm[1], d, wC.y);
            d = fma2r(vv.y, cs1i0, mul2(uu.y, cs1r0));   // D10
            fma2(Ap[2], d, wA.x); fma2(Bp[2], d, wA.y);
            fma2(Am[2], d, wC.x); fma2(Bm[2], d, wC.y);
            d = fma2r(vv.y, cs1i1, mul2(uu.y, cs1r1));   // D11
            fma2(Ap[3], d, wA.x); fma2(Bp[3], d, wA.y);
            fma2(Am[3], d, wC.x); fma2(Bm[3], d, wC.y);
        }
        // ---- shift +2 products (c = p-2 splats) ----
        {
            ull d;
            d = fma2r(vv.x, cs2i0, mul2(uu.x, cs2r0));   // D00
            fma2(Ap[4], d, wB.x); fma2(Bp[4], d, wB.y);
            fma2(Am[4], d, wD.x); fma2(Bm[4], d, wD.y);
            d = fma2r(vv.x, cs2i1, mul2(uu.x, cs2r1));   // D01
            fma2(Ap[5], d, wB.x); fma2(Bp[5], d, wB.y);
            fma2(Am[5], d, wD.x); fma2(Bm[5], d, wD.y);
            d = fma2r(vv.y, cs2i0, mul2(uu.y, cs2r0));   // D10
            fma2(Ap[6], d, wB.x); fma2(Bp[6], d, wB.y);
            fma2(Am[6], d, wD.x); fma2(Bm[6], d, wD.y);
            d = fma2r(vv.y, cs2i1, mul2(uu.y, cs2r1));   // D11
            fma2(Ap[7], d, wB.x); fma2(Bp[7], d, wB.y);
            fma2(Am[7], d, wD.x); fma2(Bm[7], d, wD.y);
        }

        // rotate splat ring
        cs2r0 = cs1r0; cs2i0 = cs1i0; cs2r1 = cs1r1; cs2i1 = cs1i1;
        cs1r0 = nsr0;  cs1i0 = nsi0;  cs1r1 = nsr1;  cs1i1 = nsi1;
    }

    if (l < Lout) {
        float2 qcf  = upk(qc);
        float qcr = qcf.x, qci = qcf.y;

        // ---- center position floats ----
        ulonglong2 xcu = sU[t + 102];          // position l + 100
        float2 x0 = upk(xcu.x), x1 = upk(xcu.y);
        float xc_x = x0.x, xc_y = x0.y, xc_z = x1.x, xc_w = x1.y;

        // ---- center-tap corrections (zcv) ----
        float wxc = ixpm_w[HALF];
        float wqc = icixpm_w[HALF];
        float pc0 = xc_x * xc_x + xc_y * xc_y;
        float pc1 = xc_z * xc_z + xc_w * xc_w;
        axp0 -= wxc * (2.f * pc0 + pc1);
        axp1 -= wxc * (2.f * pc1 + pc0);
        qcr -= wqc * (xc_x * xc_z + xc_y * xc_w);
        qci -= wqc * (xc_y * xc_z - xc_x * xc_w);

        float spm  = C00 * (pc0 + pc1);
        float phi0 = spm + 2.f * axp0;
        float phi1 = spm + 2.f * axp1;

        // ---- ici ----
        float ici0r = -(xc_z * qci + xc_w * qcr);
        float ici0i =   xc_z * qcr - xc_w * qci;
        float ici1r =   xc_x * qci - xc_y * qcr;
        float ici1i =   xc_x * qcr + xc_y * qci;

        // ---- recombine G for the 4 shift-filters k=0..3 (s=-2,-1,1,2) ----
        float Gr[4][4], Gi[4][4];
        const int sw[4] = {0, 2, 1, 3};   // mm' -> m'm
#pragma unroll
        for (int m = 0; m < 4; ++m) {
            float2 a, bb;
            a = upk(Ap[m]); bb = upk(Bp[m]);
            Gr[2][m] = a.x - bb.y;  Gi[2][m] = a.y + bb.x;
            a = upk(Ap[4 + m]); bb = upk(Bp[4 + m]);
            Gr[3][m] = a.x - bb.y;  Gi[3][m] = a.y + bb.x;
            a = upk(Am[sw[m]]); bb = upk(Bm[sw[m]]);
            Gr[1][m] = a.x + bb.y;  Gi[1][m] = bb.x - a.y;
            a = upk(Am[4 + sw[m]]); bb = upk(Bm[4 + sw[m]]);
            Gr[0][m] = a.x + bb.y;  Gi[0][m] = bb.x - a.y;
        }

        // ---- FWM combine ----
        float fwm0r = 0.f, fwm0i = 0.f, fwm1r = 0.f, fwm1i = 0.f;
        const int soff[4] = {104, 103, 101, 100};  // s=-2,-1,1,2 -> X[l+100-s]
#pragma unroll
        for (int k = 0; k < 4; ++k) {
            ulonglong2 xsu = sU[t + soff[k]];
            float2 s0f = upk(xsu.x), s1f = upk(xsu.y);
            float xs_x = s0f.x, xs_y = s0f.y, xs_z = s1f.x, xs_w = s1f.y;
            float G00r = Gr[k][0], G00i = Gi[k][0];
            float G01r = Gr[k][1], G01i = Gi[k][1];
            float G10r = Gr[k][2], G10i = Gi[k][2];
            float G11r = Gr[k][3], G11i = Gi[k][3];
            float fA0r = 2.f * G00r + G11r, fA0i = 2.f * G00i + G11i;
            float fA1r = 2.f * G11r + G00r, fA1i = 2.f * G11i + G00i;
            fwm0r += xs_x * fA0r - xs_y * fA0i;
            fwm0i += xs_x * fA0i + xs_y * fA0r;
            fwm0r += xs_z * G01r - xs_w * G01i;
            fwm0i += xs_z * G01i + xs_w * G01r;
            fwm1r += xs_z * fA1r - xs_w * fA1i;
            fwm1i += xs_z * fA1i + xs_w * fA1r;
            fwm1r += xs_x * G10r - xs_y * G10i;
            fwm1i += xs_x * G10i + xs_y * G10r;
        }

        // ---- assemble ----
        float s0, c0, s1, c1;
        sincosf(phi0, &s0, &c0);
        sincosf(phi1, &s1, &c1);
        float o0r = xc_x * c0 - xc_y * s0 + ici0r + fwm0r;
        float o0i = xc_x * s0 + xc_y * c0 + ici0i + fwm0i;
        float o1r = xc_z * c1 - xc_w * s1 + ici1r + fwm1r;
        float o1i = xc_z * s1 + xc_w * c1 + ici1i + fwm1i;

        float4* outv = (float4*)(out + ((size_t)(b * (size_t)Lout + l)) * 4);
        *outv = make_float4(o0r * rsP, o0i * rsP, o1r * rsP, o1i * rsP);
    }
}

extern "C" void kernel_launch(void* const* d_in, const int* in_sizes, int n_in,
                              void* d_out, int out_size)
{
    const float* x_real    = (const float*)d_in[0];
    const float* x_imag    = (const float*)d_in[1];
    const float* task_info = (const float*)d_in[2];
    const float* C00       = (const float*)d_in[3];
    const float* ixpm_w    = (const float*)d_in[4];
    const float* icixpm_w  = (const float*)d_in[5];
    const float* fwm_wr    = (const float*)d_in[6];
    const float* fwm_wi    = (const float*)d_in[7];

    int B = in_sizes[2] / 4;
    int M = in_sizes[0] / (B * 2);
    int Lout = M - NTAPS + 1;

    dim3 grid((Lout + TILE - 1) / TILE, B);
    snse_kernel<<<grid, TILE>>>(x_real, x_imag, task_info, C00,
                                ixpm_w, icixpm_w, fwm_wr, fwm_wi,
                                (float*)d_out, M, Lout);
}

// round 6
// speedup vs baseline: 1.3092x; 1.3092x over previous
#include <cuda_runtime.h>
#include <math.h>

#define NTAPS 201
#define HALF  100
#define NT3   204           // weight rows: taps 0..202 used + zero row 203
#define TILE  128           // threads; each thread computes 2 adjacent outputs
#define OUTS  256           // outputs per block
#define WIN   464           // window entries (need 460)

typedef unsigned long long ull;

__device__ __forceinline__ ull pk(float lo, float hi) {
    ull r; asm("mov.b64 %0, {%1, %2};" : "=l"(r) : "f"(lo), "f"(hi)); return r;
}
__device__ __forceinline__ float2 upk(ull v) {
    float2 r; asm("mov.b64 {%0, %1}, %2;" : "=f"(r.x), "=f"(r.y) : "l"(v)); return r;
}
__device__ __forceinline__ void fma2(ull &d, ull a, ull b) {
    asm("fma.rn.f32x2 %0, %1, %2, %0;" : "+l"(d) : "l"(a), "l"(b));
}
__device__ __forceinline__ ull fma2r(ull a, ull b, ull c) {
    ull r; asm("fma.rn.f32x2 %0, %1, %2, %3;" : "=l"(r) : "l"(a), "l"(b), "l"(c)); return r;
}
__device__ __forceinline__ ull mul2(ull a, ull b) {
    ull r; asm("mul.rn.f32x2 %0, %1, %2;" : "=l"(r) : "l"(a), "l"(b)); return r;
}

// sU[idx] = { (r0,i0), (r1,i1) }  at g = l0 - 2 + idx (mod M)
// sV[idx] = { (i0,-r0), (i1,-r1) }
// sW[5j+0..4] = { wrP1s|wiP1s, wrP2s|wiP2s, wrM1s|wiM1s, wrM2s|wiM2s, wxs|wqs }
// Thread t owns outputs lA = l0+2t and lB = lA+1. One product set per position
// serves both: output A at tap j (current weights), output B at tap j-1
// (previous iteration's weight registers).

__global__ __launch_bounds__(TILE, 2)
void snse_kernel(const float* __restrict__ x_real,
                 const float* __restrict__ x_imag,
                 const float* __restrict__ task_info,
                 const float* __restrict__ C00p,
                 const float* __restrict__ ixpm_w,
                 const float* __restrict__ icixpm_w,
                 const float* __restrict__ fwm_wr,
                 const float* __restrict__ fwm_wi,
                 float* __restrict__ out,
                 int M, int Lout)
{
    __shared__ ulonglong2 sU[WIN];
    __shared__ ulonglong2 sV[WIN];
    __shared__ ulonglong2 sW[NT3 * 5];

    const int b  = blockIdx.y;
    const int l0 = blockIdx.x * OUTS;
    const int t  = threadIdx.x;

    const float dbm = task_info[b * 4];
    const float P   = exp10f(dbm * 0.1f) * 0.5f;   // /Nm, Nm=2
    const float sP  = sqrtf(P);
    const float rsP = 1.0f / sP;
    const float C00 = C00p[0];

    // ---- build pre-splatted weight table (zero outside valid ranges) ----
    for (int j = t; j < NT3; j += TILE) {
        float wrP1 = (j <= 200) ? fwm_wr[2 * NTAPS + j] : 0.f;
        float wiP1 = (j <= 200) ? fwm_wi[2 * NTAPS + j] : 0.f;
        float wrP2 = (j <= 200) ? fwm_wr[3 * NTAPS + j] : 0.f;
        float wiP2 = (j <= 200) ? fwm_wi[3 * NTAPS + j] : 0.f;
        float wrM1 = (j >= 1 && j <= 201) ? fwm_wr[1 * NTAPS + (j - 1)] : 0.f;
        float wiM1 = (j >= 1 && j <= 201) ? fwm_wi[1 * NTAPS + (j - 1)] : 0.f;
        float wrM2 = (j >= 2 && j <= 202) ? fwm_wr[0 * NTAPS + (j - 2)] : 0.f;
        float wiM2 = (j >= 2 && j <= 202) ? fwm_wi[0 * NTAPS + (j - 2)] : 0.f;
        float wx   = (j <= 200) ? ixpm_w[j]   : 0.f;
        float wq   = (j <= 200) ? icixpm_w[j] : 0.f;
        sW[5 * j + 0] = make_ulonglong2(pk(wrP1, wrP1), pk(wiP1, wiP1));
        sW[5 * j + 1] = make_ulonglong2(pk(wrP2, wrP2), pk(wiP2, wiP2));
        sW[5 * j + 2] = make_ulonglong2(pk(wrM1, wrM1), pk(wiM1, wiM1));
        sW[5 * j + 3] = make_ulonglong2(pk(wrM2, wrM2), pk(wiM2, wiM2));
        sW[5 * j + 4] = make_ulonglong2(pk(wx, wx), pk(wq, wq));
    }

    // ---- load scaled x window with mod-M wrap ----
    const float* xr = x_real + (size_t)b * M * 2;
    const float* xi = x_imag + (size_t)b * M * 2;
    for (int idx = t; idx < WIN; idx += TILE) {
        int g  = l0 - 2 + idx;
        int gm = (g < 0) ? g + M : ((g >= M) ? g - M : g);
        float r0 = xr[gm * 2 + 0] * sP, r1 = xr[gm * 2 + 1] * sP;
        float i0 = xi[gm * 2 + 0] * sP, i1 = xi[gm * 2 + 1] * sP;
        sU[idx] = make_ulonglong2(pk(r0, i0), pk(r1, i1));
        sV[idx] = make_ulonglong2(pk(i0, -r0), pk(i1, -r1));
    }
    __syncthreads();

    const int base = 2 * t;        // window index of output A's position l
    const int lA = l0 + base;

    // ---- accumulators for BOTH outputs ----
    ull ApA[8], BpA[8], AmA[8], BmA[8];
    ull ApB[8], BpB[8], AmB[8], BmB[8];
#pragma unroll
    for (int k = 0; k < 8; ++k) {
        ApA[k] = BpA[k] = AmA[k] = BmA[k] = 0ULL;
        ApB[k] = BpB[k] = AmB[k] = BmB[k] = 0ULL;
    }
    ull axpA = 0ULL, axpB = 0ULL;  // (axp0, axp1) per output
    ull qcA  = 0ULL, qcB  = 0ULL;  // (qcr, qci) per output

    // splat ring: cs2 = splats of p-2, cs1 = splats of p-1 (p = lA + j)
    ull cs2r0, cs2i0, cs2r1, cs2i1;
    ull cs1r0, cs1i0, cs1r1, cs1i1;
    {
        ulonglong2 u0 = sU[base + 0];
        float2 a = upk(u0.x), c = upk(u0.y);
        cs2r0 = pk(a.x, a.x); cs2i0 = pk(a.y, a.y);
        cs2r1 = pk(c.x, c.x); cs2i1 = pk(c.y, c.y);
        ulonglong2 u1 = sU[base + 1];
        float2 d = upk(u1.x), e = upk(u1.y);
        cs1r0 = pk(d.x, d.x); cs1i0 = pk(d.y, d.y);
        cs1r1 = pk(e.x, e.x); cs1i1 = pk(e.y, e.y);
    }

    // previous-iteration weights (tap j-1 for output B); zero at j=0
    ull pA0 = 0, pA1 = 0, pB0 = 0, pB1 = 0, pC0 = 0, pC1 = 0, pD0 = 0, pD1 = 0;
    ull pE0 = 0, pE1 = 0;

#pragma unroll 2
    for (int j = 0; j < NT3; ++j) {
        const int iw = base + 2 + j;
        ulonglong2 uu  = sU[iw];
        ulonglong2 vv  = sV[iw];
        ulonglong2 wA  = sW[5 * j + 0];
        ulonglong2 wB  = sW[5 * j + 1];
        ulonglong2 wC  = sW[5 * j + 2];
        ulonglong2 wD  = sW[5 * j + 3];
        ulonglong2 wE  = sW[5 * j + 4];

        float2 f0 = upk(uu.x);
        float2 f1 = upk(uu.y);
        ull nsr0 = pk(f0.x, f0.x), nsi0 = pk(f0.y, f0.y);
        ull nsr1 = pk(f1.x, f1.x), nsi1 = pk(f1.y, f1.y);

        // ---- ixpm (powers, same ps pair feeds both outputs) ----
        float p0 = f0.x * f0.x + f0.y * f0.y;
        float p1 = f1.x * f1.x + f1.y * f1.y;
        ull ps = pk(2.f * p0 + p1, 2.f * p1 + p0);
        fma2(axpA, ps, wE.x);
        fma2(axpB, ps, pE0);

        // ---- icixpm product ----
        ull qd = fma2r(vv.x, nsi1, mul2(uu.x, nsr1));
        fma2(qcA, qd, wE.y);
        fma2(qcB, qd, pE1);

        // ---- shift +1 products (c = p-1 splats) ----
        {
            ull d;
            d = fma2r(vv.x, cs1i0, mul2(uu.x, cs1r0));   // D00
            fma2(ApA[0], d, wA.x); fma2(BpA[0], d, wA.y);
            fma2(AmA[0], d, wC.x); fma2(BmA[0], d, wC.y);
            fma2(ApB[0], d, pA0);  fma2(BpB[0], d, pA1);
            fma2(AmB[0], d, pC0);  fma2(BmB[0], d, pC1);
            d = fma2r(vv.x, cs1i1, mul2(uu.x, cs1r1));   // D01
            fma2(ApA[1], d, wA.x); fma2(BpA[1], d, wA.y);
            fma2(AmA[1], d, wC.x); fma2(BmA[1], d, wC.y);
            fma2(ApB[1], d, pA0);  fma2(BpB[1], d, pA1);
            fma2(AmB[1], d, pC0);  fma2(BmB[1], d, pC1);
            d = fma2r(vv.y, cs1i0, mul2(uu.y, cs1r0));   // D10
            fma2(ApA[2], d, wA.x); fma2(BpA[2], d, wA.y);
            fma2(AmA[2], d, wC.x); fma2(BmA[2], d, wC.y);
            fma2(ApB[2], d, pA0);  fma2(BpB[2], d, pA1);
            fma2(AmB[2], d, pC0);  fma2(BmB[2], d, pC1);
            d = fma2r(vv.y, cs1i1, mul2(uu.y, cs1r1));   // D11
            fma2(ApA[3], d, wA.x); fma2(BpA[3], d, wA.y);
            fma2(AmA[3], d, wC.x); fma2(BmA[3], d, wC.y);
            fma2(ApB[3], d, pA0);  fma2(BpB[3], d, pA1);
            fma2(AmB[3], d, pC0);  fma2(BmB[3], d, pC1);
        }
        // ---- shift +2 products (c = p-2 splats) ----
        {
            ull d;
            d = fma2r(vv.x, cs2i0, mul2(uu.x, cs2r0));   // D00
            fma2(ApA[4], d, wB.x); fma2(BpA[4], d, wB.y);
            fma2(AmA[4], d, wD.x); fma2(BmA[4], d, wD.y);
            fma2(ApB[4], d, pB0);  fma2(BpB[4], d, pB1);
            fma2(AmB[4], d, pD0);  fma2(BmB[4], d, pD1);
            d = fma2r(vv.x, cs2i1, mul2(uu.x, cs2r1));   // D01
            fma2(ApA[5], d, wB.x); fma2(BpA[5], d, wB.y);
            fma2(AmA[5], d, wD.x); fma2(BmA[5], d, wD.y);
            fma2(ApB[5], d, pB0);  fma2(BpB[5], d, pB1);
            fma2(AmB[5], d, pD0);  fma2(BmB[5], d, pD1);
            d = fma2r(vv.y, cs2i0, mul2(uu.y, cs2r0));   // D10
            fma2(ApA[6], d, wB.x); fma2(BpA[6], d, wB.y);
            fma2(AmA[6], d, wD.x); fma2(BmA[6], d, wD.y);
            fma2(ApB[6], d, pB0);  fma2(BpB[6], d, pB1);
            fma2(AmB[6], d, pD0);  fma2(BmB[6], d, pD1);
            d = fma2r(vv.y, cs2i1, mul2(uu.y, cs2r1));   // D11
            fma2(ApA[7], d, wB.x); fma2(BpA[7], d, wB.y);
            fma2(AmA[7], d, wD.x); fma2(BmA[7], d, wD.y);
            fma2(ApB[7], d, pB0);  fma2(BpB[7], d, pB1);
            fma2(AmB[7], d, pD0);  fma2(BmB[7], d, pD1);
        }

        // rotate splat ring and weight registers
        cs2r0 = cs1r0; cs2i0 = cs1i0; cs2r1 = cs1r1; cs2i1 = cs1i1;
        cs1r0 = nsr0;  cs1i0 = nsi0;  cs1r1 = nsr1;  cs1i1 = nsi1;
        pA0 = wA.x; pA1 = wA.y; pB0 = wB.x; pB1 = wB.y;
        pC0 = wC.x; pC1 = wC.y; pD0 = wD.x; pD1 = wD.y;
        pE0 = wE.x; pE1 = wE.y;
    }

    const float wxc = ixpm_w[HALF];
    const float wqc = icixpm_w[HALF];

#pragma unroll
    for (int o = 0; o < 2; ++o) {
        const int l = lA + o;
        if (l >= Lout) break;
        const int bi = base + o;
        const ull* Ap = o ? ApB : ApA;
        const ull* Bp = o ? BpB : BpA;
        const ull* Am = o ? AmB : AmA;
        const ull* Bm = o ? BmB : BmA;
        float2 axpf = upk(o ? axpB : axpA);
        float2 qcf  = upk(o ? qcB  : qcA);
        float axp0 = axpf.x, axp1 = axpf.y;
        float qcr = qcf.x, qci = qcf.y;

        // ---- center position ----
        ulonglong2 xcu = sU[bi + 102];
        float2 x0 = upk(xcu.x), x1 = upk(xcu.y);
        float xc_x = x0.x, xc_y = x0.y, xc_z = x1.x, xc_w = x1.y;

        // ---- center-tap corrections ----
        float pc0 = xc_x * xc_x + xc_y * xc_y;
        float pc1 = xc_z * xc_z + xc_w * xc_w;
        axp0 -= wxc * (2.f * pc0 + pc1);
        axp1 -= wxc * (2.f * pc1 + pc0);
        qcr -= wqc * (xc_x * xc_z + xc_y * xc_w);
        qci -= wqc * (xc_y * xc_z - xc_x * xc_w);

        float spm  = C00 * (pc0 + pc1);
        float phi0 = spm + 2.f * axp0;
        float phi1 = spm + 2.f * axp1;

        // ---- ici ----
        float ici0r = -(xc_z * qci + xc_w * qcr);
        float ici0i =   xc_z * qcr - xc_w * qci;
        float ici1r =   xc_x * qci - xc_y * qcr;
        float ici1i =   xc_x * qcr + xc_y * qci;

        // ---- recombine G (k=0..3 <-> s=-2,-1,1,2) ----
        float Gr[4][4], Gi[4][4];
        const int sw[4] = {0, 2, 1, 3};
#pragma unroll
        for (int m = 0; m < 4; ++m) {
            float2 a, bb;
            a = upk(Ap[m]); bb = upk(Bp[m]);
            Gr[2][m] = a.x - bb.y;  Gi[2][m] = a.y + bb.x;
            a = upk(Ap[4 + m]); bb = upk(Bp[4 + m]);
            Gr[3][m] = a.x - bb.y;  Gi[3][m] = a.y + bb.x;
            a = upk(Am[sw[m]]); bb = upk(Bm[sw[m]]);
            Gr[1][m] = a.x + bb.y;  Gi[1][m] = bb.x - a.y;
            a = upk(Am[4 + sw[m]]); bb = upk(Bm[4 + sw[m]]);
            Gr[0][m] = a.x + bb.y;  Gi[0][m] = bb.x - a.y;
        }

        // ---- FWM combine ----
        float fwm0r = 0.f, fwm0i = 0.f, fwm1r = 0.f, fwm1i = 0.f;
        const int soff[4] = {104, 103, 101, 100};
#pragma unroll
        for (int k = 0; k < 4; ++k) {
            ulonglong2 xsu = sU[bi + soff[k]];
            float2 s0f = upk(xsu.x), s1f = upk(xsu.y);
            float xs_x = s0f.x, xs_y = s0f.y, xs_z = s1f.x, xs_w = s1f.y;
            float G00r = Gr[k][0], G00i = Gi[k][0];
            float G01r = Gr[k][1], G01i = Gi[k][1];
            float G10r = Gr[k][2], G10i = Gi[k][2];
            float G11r = Gr[k][3], G11i = Gi[k][3];
            float fA0r = 2.f * G00r + G11r, fA0i = 2.f * G00i + G11i;
            float fA1r = 2.f * G11r + G00r, fA1i = 2.f * G11i + G00i;
            fwm0r += xs_x * fA0r - xs_y * fA0i;
            fwm0i += xs_x * fA0i + xs_y * fA0r;
            fwm0r += xs_z * G01r - xs_w * G01i;
            fwm0i += xs_z * G01i + xs_w * G01r;
            fwm1r += xs_z * fA1r - xs_w * fA1i;
            fwm1i += xs_z * fA1i + xs_w * fA1r;
            fwm1r += xs_x * G10r - xs_y * G10i;
            fwm1i += xs_x * G10i + xs_y * G10r;
        }

        // ---- assemble ----
        float s0, c0, s1, c1;
        sincosf(phi0, &s0, &c0);
        sincosf(phi1, &s1, &c1);
        float o0r = xc_x * c0 - xc_y * s0 + ici0r + fwm0r;
        float o0i = xc_x * s0 + xc_y * c0 + ici0i + fwm0i;
        float o1r = xc_z * c1 - xc_w * s1 + ici1r + fwm1r;
        float o1i = xc_z * s1 + xc_w * c1 + ici1i + fwm1i;

        float4* outv = (float4*)(out + ((size_t)(b * (size_t)Lout + l)) * 4);
        *outv = make_float4(o0r * rsP, o0i * rsP, o1r * rsP, o1i * rsP);
    }
}

extern "C" void kernel_launch(void* const* d_in, const int* in_sizes, int n_in,
                              void* d_out, int out_size)
{
    const float* x_real    = (const float*)d_in[0];
    const float* x_imag    = (const float*)d_in[1];
    const float* task_info = (const float*)d_in[2];
    const float* C00       = (const float*)d_in[3];
    const float* ixpm_w    = (const float*)d_in[4];
    const float* icixpm_w  = (const float*)d_in[5];
    const float* fwm_wr    = (const float*)d_in[6];
    const float* fwm_wi    = (const float*)d_in[7];

    int B = in_sizes[2] / 4;
    int M = in_sizes[0] / (B * 2);
    int Lout = M - NTAPS + 1;

    dim3 grid((Lout + OUTS - 1) / OUTS, B);
    snse_kernel<<<grid, TILE>>>(x_real, x_imag, task_info, C00,
                                ixpm_w, icixpm_w, fwm_wr, fwm_wi,
                                (float*)d_out, M, Lout);
}

// round 7
// speedup vs baseline: 1.3853x; 1.0581x over previous
#include <cuda_runtime.h>
#include <math.h>

#define NTAPS 201
#define HALF  100
#define NT3   204           // weight rows: taps 0..202 used + zero row 203; 204 = 6*34
#define TILE  128           // threads; each thread computes 2 adjacent outputs
#define OUTS  256           // outputs per block
#define WIN   464           // window entries (need 460)

typedef unsigned long long ull;

__device__ __forceinline__ ull pk(float lo, float hi) {
    ull r; asm("mov.b64 %0, {%1, %2};" : "=l"(r) : "f"(lo), "f"(hi)); return r;
}
__device__ __forceinline__ float2 upk(ull v) {
    float2 r; asm("mov.b64 {%0, %1}, %2;" : "=f"(r.x), "=f"(r.y) : "l"(v)); return r;
}
__device__ __forceinline__ void fma2(ull &d, ull a, ull b) {
    asm("fma.rn.f32x2 %0, %1, %2, %0;" : "+l"(d) : "l"(a), "l"(b));
}
__device__ __forceinline__ ull fma2r(ull a, ull b, ull c) {
    ull r; asm("fma.rn.f32x2 %0, %1, %2, %3;" : "=l"(r) : "l"(a), "l"(b), "l"(c)); return r;
}
__device__ __forceinline__ ull mul2(ull a, ull b) {
    ull r; asm("mul.rn.f32x2 %0, %1, %2;" : "=l"(r) : "l"(a), "l"(b)); return r;
}

// sU[idx] = { (r0,i0), (r1,i1) }  at g = l0 - 2 + idx (mod M)
// sV[idx] = { (i0,-r0), (i1,-r1) }
// sW[5j+0..4] = { wrP1s|wiP1s, wrP2s|wiP2s, wrM1s|wiM1s, wrM2s|wiM2s, wxs|wqs }
// Thread t owns outputs lA = l0+2t and lB = lA+1. One product set per position
// serves both: output A at tap j (current weights), output B at tap j-1
// (previous iteration's weights). Loop unrolled by 6 = lcm(splat-ring period 3,
// weight-history period 2) so ALL loop-carried rotations are register-renamed.

__global__ __launch_bounds__(TILE, 2)
void snse_kernel(const float* __restrict__ x_real,
                 const float* __restrict__ x_imag,
                 const float* __restrict__ task_info,
                 const float* __restrict__ C00p,
                 const float* __restrict__ ixpm_w,
                 const float* __restrict__ icixpm_w,
                 const float* __restrict__ fwm_wr,
                 const float* __restrict__ fwm_wi,
                 float* __restrict__ out,
                 int M, int Lout)
{
    __shared__ ulonglong2 sU[WIN];
    __shared__ ulonglong2 sV[WIN];
    __shared__ ulonglong2 sW[NT3 * 5];

    const int b  = blockIdx.y;
    const int l0 = blockIdx.x * OUTS;
    const int t  = threadIdx.x;

    const float dbm = task_info[b * 4];
    const float P   = exp10f(dbm * 0.1f) * 0.5f;   // /Nm, Nm=2
    const float sP  = sqrtf(P);
    const float rsP = 1.0f / sP;
    const float C00 = C00p[0];

    // ---- build pre-splatted weight table (zero outside valid ranges) ----
    for (int j = t; j < NT3; j += TILE) {
        float wrP1 = (j <= 200) ? fwm_wr[2 * NTAPS + j] : 0.f;
        float wiP1 = (j <= 200) ? fwm_wi[2 * NTAPS + j] : 0.f;
        float wrP2 = (j <= 200) ? fwm_wr[3 * NTAPS + j] : 0.f;
        float wiP2 = (j <= 200) ? fwm_wi[3 * NTAPS + j] : 0.f;
        float wrM1 = (j >= 1 && j <= 201) ? fwm_wr[1 * NTAPS + (j - 1)] : 0.f;
        float wiM1 = (j >= 1 && j <= 201) ? fwm_wi[1 * NTAPS + (j - 1)] : 0.f;
        float wrM2 = (j >= 2 && j <= 202) ? fwm_wr[0 * NTAPS + (j - 2)] : 0.f;
        float wiM2 = (j >= 2 && j <= 202) ? fwm_wi[0 * NTAPS + (j - 2)] : 0.f;
        float wx   = (j <= 200) ? ixpm_w[j]   : 0.f;
        float wq   = (j <= 200) ? icixpm_w[j] : 0.f;
        sW[5 * j + 0] = make_ulonglong2(pk(wrP1, wrP1), pk(wiP1, wiP1));
        sW[5 * j + 1] = make_ulonglong2(pk(wrP2, wrP2), pk(wiP2, wiP2));
        sW[5 * j + 2] = make_ulonglong2(pk(wrM1, wrM1), pk(wiM1, wiM1));
        sW[5 * j + 3] = make_ulonglong2(pk(wrM2, wrM2), pk(wiM2, wiM2));
        sW[5 * j + 4] = make_ulonglong2(pk(wx, wx), pk(wq, wq));
    }

    // ---- load scaled x window with mod-M wrap ----
    const float* xr = x_real + (size_t)b * M * 2;
    const float* xi = x_imag + (size_t)b * M * 2;
    for (int idx = t; idx < WIN; idx += TILE) {
        int g  = l0 - 2 + idx;
        int gm = (g < 0) ? g + M : ((g >= M) ? g - M : g);
        float r0 = xr[gm * 2 + 0] * sP, r1 = xr[gm * 2 + 1] * sP;
        float i0 = xi[gm * 2 + 0] * sP, i1 = xi[gm * 2 + 1] * sP;
        sU[idx] = make_ulonglong2(pk(r0, i0), pk(r1, i1));
        sV[idx] = make_ulonglong2(pk(i0, -r0), pk(i1, -r1));
    }
    __syncthreads();

    const int base = 2 * t;        // window index of output A's position l
    const int lA = l0 + base;

    // ---- accumulators for BOTH outputs ----
    ull ApA[8], BpA[8], AmA[8], BmA[8];
    ull ApB[8], BpB[8], AmB[8], BmB[8];
#pragma unroll
    for (int k = 0; k < 8; ++k) {
        ApA[k] = BpA[k] = AmA[k] = BmA[k] = 0ULL;
        ApB[k] = BpB[k] = AmB[k] = BmB[k] = 0ULL;
    }
    ull axpA = 0ULL, axpB = 0ULL;  // (axp0, axp1) per output
    ull qcA  = 0ULL, qcB  = 0ULL;  // (qcr, qci) per output

    // splat ring: cs2 = splats of p-2, cs1 = splats of p-1 (p = lA + j)
    ull cs2r0, cs2i0, cs2r1, cs2i1;
    ull cs1r0, cs1i0, cs1r1, cs1i1;
    {
        ulonglong2 u0 = sU[base + 0];
        float2 a = upk(u0.x), c = upk(u0.y);
        cs2r0 = pk(a.x, a.x); cs2i0 = pk(a.y, a.y);
        cs2r1 = pk(c.x, c.x); cs2i1 = pk(c.y, c.y);
        ulonglong2 u1 = sU[base + 1];
        float2 d = upk(u1.x), e = upk(u1.y);
        cs1r0 = pk(d.x, d.x); cs1i0 = pk(d.y, d.y);
        cs1r1 = pk(e.x, e.x); cs1i1 = pk(e.y, e.y);
    }

    // previous-iteration weights (tap j-1 for output B); zero at j=0
    ull pA0 = 0, pA1 = 0, pB0 = 0, pB1 = 0, pC0 = 0, pC1 = 0, pD0 = 0, pD1 = 0;
    ull pE0 = 0, pE1 = 0;

#pragma unroll 6
    for (int j = 0; j < NT3; ++j) {
        const int iw = base + 2 + j;
        ulonglong2 uu  = sU[iw];
        ulonglong2 vv  = sV[iw];
        ulonglong2 wA  = sW[5 * j + 0];
        ulonglong2 wB  = sW[5 * j + 1];
        ulonglong2 wC  = sW[5 * j + 2];
        ulonglong2 wD  = sW[5 * j + 3];
        ulonglong2 wE  = sW[5 * j + 4];

        float2 f0 = upk(uu.x);
        float2 f1 = upk(uu.y);
        ull nsr0 = pk(f0.x, f0.x), nsi0 = pk(f0.y, f0.y);
        ull nsr1 = pk(f1.x, f1.x), nsi1 = pk(f1.y, f1.y);

        // ---- ixpm (powers, same ps pair feeds both outputs) ----
        float p0 = f0.x * f0.x + f0.y * f0.y;
        float p1 = f1.x * f1.x + f1.y * f1.y;
        ull ps = pk(2.f * p0 + p1, 2.f * p1 + p0);
        fma2(axpA, ps, wE.x);
        fma2(axpB, ps, pE0);

        // ---- icixpm product ----
        ull qd = fma2r(vv.x, nsi1, mul2(uu.x, nsr1));
        fma2(qcA, qd, wE.y);
        fma2(qcB, qd, pE1);

        // ---- shift +1 products (c = p-1 splats) ----
        {
            ull d;
            d = fma2r(vv.x, cs1i0, mul2(uu.x, cs1r0));   // D00
            fma2(ApA[0], d, wA.x); fma2(BpA[0], d, wA.y);
            fma2(AmA[0], d, wC.x); fma2(BmA[0], d, wC.y);
            fma2(ApB[0], d, pA0);  fma2(BpB[0], d, pA1);
            fma2(AmB[0], d, pC0);  fma2(BmB[0], d, pC1);
            d = fma2r(vv.x, cs1i1, mul2(uu.x, cs1r1));   // D01
            fma2(ApA[1], d, wA.x); fma2(BpA[1], d, wA.y);
            fma2(AmA[1], d, wC.x); fma2(BmA[1], d, wC.y);
            fma2(ApB[1], d, pA0);  fma2(BpB[1], d, pA1);
            fma2(AmB[1], d, pC0);  fma2(BmB[1], d, pC1);
            d = fma2r(vv.y, cs1i0, mul2(uu.y, cs1r0));   // D10
            fma2(ApA[2], d, wA.x); fma2(BpA[2], d, wA.y);
            fma2(AmA[2], d, wC.x); fma2(BmA[2], d, wC.y);
            fma2(ApB[2], d, pA0);  fma2(BpB[2], d, pA1);
            fma2(AmB[2], d, pC0);  fma2(BmB[2], d, pC1);
            d = fma2r(vv.y, cs1i1, mul2(uu.y, cs1r1));   // D11
            fma2(ApA[3], d, wA.x); fma2(BpA[3], d, wA.y);
            fma2(AmA[3], d, wC.x); fma2(BmA[3], d, wC.y);
            fma2(ApB[3], d, pA0);  fma2(BpB[3], d, pA1);
            fma2(AmB[3], d, pC0);  fma2(BmB[3], d, pC1);
        }
        // ---- shift +2 products (c = p-2 splats) ----
        {
            ull d;
            d = fma2r(vv.x, cs2i0, mul2(uu.x, cs2r0));   // D00
            fma2(ApA[4], d, wB.x); fma2(BpA[4], d, wB.y);
            fma2(AmA[4], d, wD.x); fma2(BmA[4], d, wD.y);
            fma2(ApB[4], d, pB0);  fma2(BpB[4], d, pB1);
            fma2(AmB[4], d, pD0);  fma2(BmB[4], d, pD1);
            d = fma2r(vv.x, cs2i1, mul2(uu.x, cs2r1));   // D01
            fma2(ApA[5], d, wB.x); fma2(BpA[5], d, wB.y);
            fma2(AmA[5], d, wD.x); fma2(BmA[5], d, wD.y);
            fma2(ApB[5], d, pB0);  fma2(BpB[5], d, pB1);
            fma2(AmB[5], d, pD0);  fma2(BmB[5], d, pD1);
            d = fma2r(vv.y, cs2i0, mul2(uu.y, cs2r0));   // D10
            fma2(ApA[6], d, wB.x); fma2(BpA[6], d, wB.y);
            fma2(AmA[6], d, wD.x); fma2(BmA[6], d, wD.y);
            fma2(ApB[6], d, pB0);  fma2(BpB[6], d, pB1);
            fma2(AmB[6], d, pD0);  fma2(BmB[6], d, pD1);
            d = fma2r(vv.y, cs2i1, mul2(uu.y, cs2r1));   // D11
            fma2(ApA[7], d, wB.x); fma2(BpA[7], d, wB.y);
            fma2(AmA[7], d, wD.x); fma2(BmA[7], d, wD.y);
            fma2(ApB[7], d, pB0);  fma2(BpB[7], d, pB1);
            fma2(AmB[7], d, pD0);  fma2(BmB[7], d, pD1);
        }

        // rotate splat ring and weight registers (renamed away by unroll 6)
        cs2r0 = cs1r0; cs2i0 = cs1i0; cs2r1 = cs1r1; cs2i1 = cs1i1;
        cs1r0 = nsr0;  cs1i0 = nsi0;  cs1r1 = nsr1;  cs1i1 = nsi1;
        pA0 = wA.x; pA1 = wA.y; pB0 = wB.x; pB1 = wB.y;
        pC0 = wC.x; pC1 = wC.y; pD0 = wD.x; pD1 = wD.y;
        pE0 = wE.x; pE1 = wE.y;
    }

    const float wxc = ixpm_w[HALF];
    const float wqc = icixpm_w[HALF];

#pragma unroll
    for (int o = 0; o < 2; ++o) {
        const int l = lA + o;
        if (l >= Lout) break;
        const int bi = base + o;
        const ull* Ap = o ? ApB : ApA;
        const ull* Bp = o ? BpB : BpA;
        const ull* Am = o ? AmB : AmA;
        const ull* Bm = o ? BmB : BmA;
        float2 axpf = upk(o ? axpB : axpA);
        float2 qcf  = upk(o ? qcB  : qcA);
        float axp0 = axpf.x, axp1 = axpf.y;
        float qcr = qcf.x, qci = qcf.y;

        // ---- center position ----
        ulonglong2 xcu = sU[bi + 102];
        float2 x0 = upk(xcu.x), x1 = upk(xcu.y);
        float xc_x = x0.x, xc_y = x0.y, xc_z = x1.x, xc_w = x1.y;

        // ---- center-tap corrections ----
        float pc0 = xc_x * xc_x + xc_y * xc_y;
        float pc1 = xc_z * xc_z + xc_w * xc_w;
        axp0 -= wxc * (2.f * pc0 + pc1);
        axp1 -= wxc * (2.f * pc1 + pc0);
        qcr -= wqc * (xc_x * xc_z + xc_y * xc_w);
        qci -= wqc * (xc_y * xc_z - xc_x * xc_w);

        float spm  = C00 * (pc0 + pc1);
        float phi0 = spm + 2.f * axp0;
        float phi1 = spm + 2.f * axp1;

        // ---- ici ----
        float ici0r = -(xc_z * qci + xc_w * qcr);
        float ici0i =   xc_z * qcr - xc_w * qci;
        float ici1r =   xc_x * qci - xc_y * qcr;
        float ici1i =   xc_x * qcr + xc_y * qci;

        // ---- recombine G (k=0..3 <-> s=-2,-1,1,2) ----
        float Gr[4][4], Gi[4][4];
        const int sw[4] = {0, 2, 1, 3};
#pragma unroll
        for (int m = 0; m < 4; ++m) {
            float2 a, bb;
            a = upk(Ap[m]); bb = upk(Bp[m]);
            Gr[2][m] = a.x - bb.y;  Gi[2][m] = a.y + bb.x;
            a = upk(Ap[4 + m]); bb = upk(Bp[4 + m]);
            Gr[3][m] = a.x - bb.y;  Gi[3][m] = a.y + bb.x;
            a = upk(Am[sw[m]]); bb = upk(Bm[sw[m]]);
            Gr[1][m] = a.x + bb.y;  Gi[1][m] = bb.x - a.y;
            a = upk(Am[4 + sw[m]]); bb = upk(Bm[4 + sw[m]]);
            Gr[0][m] = a.x + bb.y;  Gi[0][m] = bb.x - a.y;
        }

        // ---- FWM combine ----
        float fwm0r = 0.f, fwm0i = 0.f, fwm1r = 0.f, fwm1i = 0.f;
        const int soff[4] = {104, 103, 101, 100};
#pragma unroll
        for (int k = 0; k < 4; ++k) {
            ulonglong2 xsu = sU[bi + soff[k]];
            float2 s0f = upk(xsu.x), s1f = upk(xsu.y);
            float xs_x = s0f.x, xs_y = s0f.y, xs_z = s1f.x, xs_w = s1f.y;
            float G00r = Gr[k][0], G00i = Gi[k][0];
            float G01r = Gr[k][1], G01i = Gi[k][1];
            float G10r = Gr[k][2], G10i = Gi[k][2];
            float G11r = Gr[k][3], G11i = Gi[k][3];
            float fA0r = 2.f * G00r + G11r, fA0i = 2.f * G00i + G11i;
            float fA1r = 2.f * G11r + G00r, fA1i = 2.f * G11i + G00i;
            fwm0r += xs_x * fA0r - xs_y * fA0i;
            fwm0i += xs_x * fA0i + xs_y * fA0r;
            fwm0r += xs_z * G01r - xs_w * G01i;
            fwm0i += xs_z * G01i + xs_w * G01r;
            fwm1r += xs_z * fA1r - xs_w * fA1i;
            fwm1i += xs_z * fA1i + xs_w * fA1r;
            fwm1r += xs_x * G10r - xs_y * G10i;
            fwm1i += xs_x * G10i + xs_y * G10r;
        }

        // ---- assemble ----
        float s0, c0, s1, c1;
        sincosf(phi0, &s0, &c0);
        sincosf(phi1, &s1, &c1);
        float o0r = xc_x * c0 - xc_y * s0 + ici0r + fwm0r;
        float o0i = xc_x * s0 + xc_y * c0 + ici0i + fwm0i;
        float o1r = xc_z * c1 - xc_w * s1 + ici1r + fwm1r;
        float o1i = xc_z * s1 + xc_w * c1 + ici1i + fwm1i;

        float4* outv = (float4*)(out + ((size_t)(b * (size_t)Lout + l)) * 4);
        *outv = make_float4(o0r * rsP, o0i * rsP, o1r * rsP, o1i * rsP);
    }
}

extern "C" void kernel_launch(void* const* d_in, const int* in_sizes, int n_in,
                              void* d_out, int out_size)
{
    const float* x_real    = (const float*)d_in[0];
    const float* x_imag    = (const float*)d_in[1];
    const float* task_info = (const float*)d_in[2];
    const float* C00       = (const float*)d_in[3];
    const float* ixpm_w    = (const float*)d_in[4];
    const float* icixpm_w  = (const float*)d_in[5];
    const float* fwm_wr    = (const float*)d_in[6];
    const float* fwm_wi    = (const float*)d_in[7];

    int B = in_sizes[2] / 4;
    int M = in_sizes[0] / (B * 2);
    int Lout = M - NTAPS + 1;

    dim3 grid((Lout + OUTS - 1) / OUTS, B);
    snse_kernel<<<grid, TILE>>>(x_real, x_imag, task_info, C00,
                                ixpm_w, icixpm_w, fwm_wr, fwm_wi,
                                (float*)d_out, M, Lout);
}

// round 8
// speedup vs baseline: 1.4427x; 1.0414x over previous
#include <cuda_runtime.h>
#include <math.h>

#define NTAPS 201
#define HALF  100
#define NT3   204           // weight rows: taps 0..202 used + zero row 203
#define TILE  128           // threads; each thread computes 2 adjacent outputs
#define OUTS  256           // outputs per block
#define WIN   464           // window entries (need 461)
#define ST    488           // skewed stride per product array (max sp = 459+28=487)
#define NARR  10
#define DYNBYTES (NARR * ST * 8)

typedef unsigned long long ull;

__device__ __forceinline__ ull pk(float lo, float hi) {
    ull r; asm("mov.b64 %0, {%1, %2};" : "=l"(r) : "f"(lo), "f"(hi)); return r;
}
__device__ __forceinline__ float2 upk(ull v) {
    float2 r; asm("mov.b64 {%0, %1}, %2;" : "=f"(r.x), "=f"(r.y) : "l"(v)); return r;
}
__device__ __forceinline__ void fma2(ull &d, ull a, ull b) {
    asm("fma.rn.f32x2 %0, %1, %2, %0;" : "+l"(d) : "l"(a), "l"(b));
}

// Phase 1 precomputes per window position p (shared across all threads):
//   sD[0..3][p] = X_m[p]*conj(X_m'[p-1])   mm' = 00,01,10,11   (shift +1)
//   sD[4..7][p] = X_m[p]*conj(X_m'[p-2])                        (shift +2)
//   sD[8][p]    = X_0[p]*conj(X_1[p])                           (icixpm q)
//   sD[9][p]    = (2p0+p1, 2p1+p0)                              (ixpm powers)
// stored at skewed index sp = p + (p>>4) for conflict-free stride-2 reads.
// Phase 2: thread t owns outputs lA = l0+2t and lB = lA+1; one product read
// feeds output A at tap j (weights w[j]) and B at tap j-1 (previous weights).

__global__ __launch_bounds__(TILE, 2)
void snse_kernel(const float* __restrict__ x_real,
                 const float* __restrict__ x_imag,
                 const float* __restrict__ task_info,
                 const float* __restrict__ C00p,
                 const float* __restrict__ ixpm_w,
                 const float* __restrict__ icixpm_w,
                 const float* __restrict__ fwm_wr,
                 const float* __restrict__ fwm_wi,
                 float* __restrict__ out,
                 int M, int Lout)
{
    __shared__ ulonglong2 sU[WIN];
    __shared__ ulonglong2 sW[NT3 * 5];
    extern __shared__ ull sD[];        // NARR arrays of ST ull each

    const int b  = blockIdx.y;
    const int l0 = blockIdx.x * OUTS;
    const int t  = threadIdx.x;

    const float dbm = task_info[b * 4];
    const float P   = exp10f(dbm * 0.1f) * 0.5f;   // /Nm, Nm=2
    const float sP  = sqrtf(P);
    const float rsP = 1.0f / sP;
    const float C00 = C00p[0];

    // ---- build pre-splatted weight table (zero outside valid ranges) ----
    for (int j = t; j < NT3; j += TILE) {
        float wrP1 = (j <= 200) ? fwm_wr[2 * NTAPS + j] : 0.f;
        float wiP1 = (j <= 200) ? fwm_wi[2 * NTAPS + j] : 0.f;
        float wrP2 = (j <= 200) ? fwm_wr[3 * NTAPS + j] : 0.f;
        float wiP2 = (j <= 200) ? fwm_wi[3 * NTAPS + j] : 0.f;
        float wrM1 = (j >= 1 && j <= 201) ? fwm_wr[1 * NTAPS + (j - 1)] : 0.f;
        float wiM1 = (j >= 1 && j <= 201) ? fwm_wi[1 * NTAPS + (j - 1)] : 0.f;
        float wrM2 = (j >= 2 && j <= 202) ? fwm_wr[0 * NTAPS + (j - 2)] : 0.f;
        float wiM2 = (j >= 2 && j <= 202) ? fwm_wi[0 * NTAPS + (j - 2)] : 0.f;
        float wx   = (j <= 200) ? ixpm_w[j]   : 0.f;
        float wq   = (j <= 200) ? icixpm_w[j] : 0.f;
        sW[5 * j + 0] = make_ulonglong2(pk(wrP1, wrP1), pk(wiP1, wiP1));
        sW[5 * j + 1] = make_ulonglong2(pk(wrP2, wrP2), pk(wiP2, wiP2));
        sW[5 * j + 2] = make_ulonglong2(pk(wrM1, wrM1), pk(wiM1, wiM1));
        sW[5 * j + 3] = make_ulonglong2(pk(wrM2, wrM2), pk(wiM2, wiM2));
        sW[5 * j + 4] = make_ulonglong2(pk(wx, wx), pk(wq, wq));
    }

    // ---- load scaled x window with mod-M wrap ----
    const float* xr = x_real + (size_t)b * M * 2;
    const float* xi = x_imag + (size_t)b * M * 2;
    for (int idx = t; idx < WIN; idx += TILE) {
        int g  = l0 - 2 + idx;
        int gm = (g < 0) ? g + M : ((g >= M) ? g - M : g);
        float r0 = xr[gm * 2 + 0] * sP, r1 = xr[gm * 2 + 1] * sP;
        float i0 = xi[gm * 2 + 0] * sP, i1 = xi[gm * 2 + 1] * sP;
        sU[idx] = make_ulonglong2(pk(r0, i0), pk(r1, i1));
    }
    __syncthreads();

    // ---- phase 1: per-position products into skewed shared arrays ----
    for (int idx = t; idx < 459; idx += TILE) {
        int p = idx + 2;
        ulonglong2 u0 = sU[p], u1 = sU[p - 1], u2 = sU[p - 2];
        float2 f0 = upk(u0.x), f1 = upk(u0.y);
        float2 a0 = upk(u1.x), a1 = upk(u1.y);
        float2 b0 = upk(u2.x), b1 = upk(u2.y);
        int sp = p + (p >> 4);
        sD[0 * ST + sp] = pk(f0.x * a0.x + f0.y * a0.y, f0.y * a0.x - f0.x * a0.y);
        sD[1 * ST + sp] = pk(f0.x * a1.x + f0.y * a1.y, f0.y * a1.x - f0.x * a1.y);
        sD[2 * ST + sp] = pk(f1.x * a0.x + f1.y * a0.y, f1.y * a0.x - f1.x * a0.y);
        sD[3 * ST + sp] = pk(f1.x * a1.x + f1.y * a1.y, f1.y * a1.x - f1.x * a1.y);
        sD[4 * ST + sp] = pk(f0.x * b0.x + f0.y * b0.y, f0.y * b0.x - f0.x * b0.y);
        sD[5 * ST + sp] = pk(f0.x * b1.x + f0.y * b1.y, f0.y * b1.x - f0.x * b1.y);
        sD[6 * ST + sp] = pk(f1.x * b0.x + f1.y * b0.y, f1.y * b0.x - f1.x * b0.y);
        sD[7 * ST + sp] = pk(f1.x * b1.x + f1.y * b1.y, f1.y * b1.x - f1.x * b1.y);
        sD[8 * ST + sp] = pk(f0.x * f1.x + f0.y * f1.y, f0.y * f1.x - f0.x * f1.y);
        float p0 = f0.x * f0.x + f0.y * f0.y;
        float p1 = f1.x * f1.x + f1.y * f1.y;
        sD[9 * ST + sp] = pk(2.f * p0 + p1, 2.f * p1 + p0);
    }
    __syncthreads();

    const int base = 2 * t;        // window index of output A's position l
    const int lA = l0 + base;

    // ---- accumulators for BOTH outputs ----
    ull ApA[8], BpA[8], AmA[8], BmA[8];
    ull ApB[8], BpB[8], AmB[8], BmB[8];
#pragma unroll
    for (int k = 0; k < 8; ++k) {
        ApA[k] = BpA[k] = AmA[k] = BmA[k] = 0ULL;
        ApB[k] = BpB[k] = AmB[k] = BmB[k] = 0ULL;
    }
    ull axpA = 0ULL, axpB = 0ULL;  // (axp0, axp1) per output
    ull qcA  = 0ULL, qcB  = 0ULL;  // (qcr, qci) per output

    // previous-iteration weights (tap j-1 for output B); zero at j=0
    ull pA0 = 0, pA1 = 0, pB0 = 0, pB1 = 0, pC0 = 0, pC1 = 0, pD0 = 0, pD1 = 0;
    ull pE0 = 0, pE1 = 0;

#pragma unroll 2
    for (int j = 0; j < NT3; ++j) {
        const int e  = base + 2 + j;
        const int sp = e + (e >> 4);
        ull d0 = sD[0 * ST + sp], d1 = sD[1 * ST + sp];
        ull d2 = sD[2 * ST + sp], d3 = sD[3 * ST + sp];
        ull d4 = sD[4 * ST + sp], d5 = sD[5 * ST + sp];
        ull d6 = sD[6 * ST + sp], d7 = sD[7 * ST + sp];
        ull qd = sD[8 * ST + sp], ps = sD[9 * ST + sp];
        ulonglong2 wA = sW[5 * j + 0];
        ulonglong2 wB = sW[5 * j + 1];
        ulonglong2 wC = sW[5 * j + 2];
        ulonglong2 wD = sW[5 * j + 3];
        ulonglong2 wE = sW[5 * j + 4];

        fma2(axpA, ps, wE.x);  fma2(axpB, ps, pE0);
        fma2(qcA,  qd, wE.y);  fma2(qcB,  qd, pE1);

        // shift +1 products
        fma2(ApA[0], d0, wA.x); fma2(BpA[0], d0, wA.y);
        fma2(AmA[0], d0, wC.x); fma2(BmA[0], d0, wC.y);
        fma2(ApB[0], d0, pA0);  fma2(BpB[0], d0, pA1);
        fma2(AmB[0], d0, pC0);  fma2(BmB[0], d0, pC1);

        fma2(ApA[1], d1, wA.x); fma2(BpA[1], d1, wA.y);
        fma2(AmA[1], d1, wC.x); fma2(BmA[1], d1, wC.y);
        fma2(ApB[1], d1, pA0);  fma2(BpB[1], d1, pA1);
        fma2(AmB[1], d1, pC0);  fma2(BmB[1], d1, pC1);

        fma2(ApA[2], d2, wA.x); fma2(BpA[2], d2, wA.y);
        fma2(AmA[2], d2, wC.x); fma2(BmA[2], d2, wC.y);
        fma2(ApB[2], d2, pA0);  fma2(BpB[2], d2, pA1);
        fma2(AmB[2], d2, pC0);  fma2(BmB[2], d2, pC1);

        fma2(ApA[3], d3, wA.x); fma2(BpA[3], d3, wA.y);
        fma2(AmA[3], d3, wC.x); fma2(BmA[3], d3, wC.y);
        fma2(ApB[3], d3, pA0);  fma2(BpB[3], d3, pA1);
        fma2(AmB[3], d3, pC0);  fma2(BmB[3], d3, pC1);

        // shift +2 products
        fma2(ApA[4], d4, wB.x); fma2(BpA[4], d4, wB.y);
        fma2(AmA[4], d4, wD.x); fma2(BmA[4], d4, wD.y);
        fma2(ApB[4], d4, pB0);  fma2(BpB[4], d4, pB1);
        fma2(AmB[4], d4, pD0);  fma2(BmB[4], d4, pD1);

        fma2(ApA[5], d5, wB.x); fma2(BpA[5], d5, wB.y);
        fma2(AmA[5], d5, wD.x); fma2(BmA[5], d5, wD.y);
        fma2(ApB[5], d5, pB0);  fma2(BpB[5], d5, pB1);
        fma2(AmB[5], d5, pD0);  fma2(BmB[5], d5, pD1);

        fma2(ApA[6], d6, wB.x); fma2(BpA[6], d6, wB.y);
        fma2(AmA[6], d6, wD.x); fma2(BmA[6], d6, wD.y);
        fma2(ApB[6], d6, pB0);  fma2(BpB[6], d6, pB1);
        fma2(AmB[6], d6, pD0);  fma2(BmB[6], d6, pD1);

        fma2(ApA[7], d7, wB.x); fma2(BpA[7], d7, wB.y);
        fma2(AmA[7], d7, wD.x); fma2(BmA[7], d7, wD.y);
        fma2(ApB[7], d7, pB0);  fma2(BpB[7], d7, pB1);
        fma2(AmB[7], d7, pD0);  fma2(BmB[7], d7, pD1);

        // weight history (renamed away by unroll 2)
        pA0 = wA.x; pA1 = wA.y; pB0 = wB.x; pB1 = wB.y;
        pC0 = wC.x; pC1 = wC.y; pD0 = wD.x; pD1 = wD.y;
        pE0 = wE.x; pE1 = wE.y;
    }

    const float wxc = ixpm_w[HALF];
    const float wqc = icixpm_w[HALF];

#pragma unroll
    for (int o = 0; o < 2; ++o) {
        const int l = lA + o;
        if (l >= Lout) break;
        const int bi = base + o;
        const ull* Ap = o ? ApB : ApA;
        const ull* Bp = o ? BpB : BpA;
        const ull* Am = o ? AmB : AmA;
        const ull* Bm = o ? BmB : BmA;
        float2 axpf = upk(o ? axpB : axpA);
        float2 qcf  = upk(o ? qcB  : qcA);
        float axp0 = axpf.x, axp1 = axpf.y;
        float qcr = qcf.x, qci = qcf.y;

        // ---- center position ----
        ulonglong2 xcu = sU[bi + 102];
        float2 x0 = upk(xcu.x), x1 = upk(xcu.y);
        float xc_x = x0.x, xc_y = x0.y, xc_z = x1.x, xc_w = x1.y;

        // ---- center-tap corrections ----
        float pc0 = xc_x * xc_x + xc_y * xc_y;
        float pc1 = xc_z * xc_z + xc_w * xc_w;
        axp0 -= wxc * (2.f * pc0 + pc1);
        axp1 -= wxc * (2.f * pc1 + pc0);
        qcr -= wqc * (xc_x * xc_z + xc_y * xc_w);
        qci -= wqc * (xc_y * xc_z - xc_x * xc_w);

        float spm  = C00 * (pc0 + pc1);
        float phi0 = spm + 2.f * axp0;
        float phi1 = spm + 2.f * axp1;

        // ---- ici ----
        float ici0r = -(xc_z * qci + xc_w * qcr);
        float ici0i =   xc_z * qcr - xc_w * qci;
        float ici1r =   xc_x * qci - xc_y * qcr;
        float ici1i =   xc_x * qcr + xc_y * qci;

        // ---- recombine G (k=0..3 <-> s=-2,-1,1,2) ----
        float Gr[4][4], Gi[4][4];
        const int sw[4] = {0, 2, 1, 3};
#pragma unroll
        for (int m = 0; m < 4; ++m) {
            float2 a, bb;
            a = upk(Ap[m]); bb = upk(Bp[m]);
            Gr[2][m] = a.x - bb.y;  Gi[2][m] = a.y + bb.x;
            a = upk(Ap[4 + m]); bb = upk(Bp[4 + m]);
            Gr[3][m] = a.x - bb.y;  Gi[3][m] = a.y + bb.x;
            a = upk(Am[sw[m]]); bb = upk(Bm[sw[m]]);
            Gr[1][m] = a.x + bb.y;  Gi[1][m] = bb.x - a.y;
            a = upk(Am[4 + sw[m]]); bb = upk(Bm[4 + sw[m]]);
            Gr[0][m] = a.x + bb.y;  Gi[0][m] = bb.x - a.y;
        }

        // ---- FWM combine ----
        float fwm0r = 0.f, fwm0i = 0.f, fwm1r = 0.f, fwm1i = 0.f;
        const int soff[4] = {104, 103, 101, 100};
#pragma unroll
        for (int k = 0; k < 4; ++k) {
            ulonglong2 xsu = sU[bi + soff[k]];
            float2 s0f = upk(xsu.x), s1f = upk(xsu.y);
            float xs_x = s0f.x, xs_y = s0f.y, xs_z = s1f.x, xs_w = s1f.y;
            float G00r = Gr[k][0], G00i = Gi[k][0];
            float G01r = Gr[k][1], G01i = Gi[k][1];
            float G10r = Gr[k][2], G10i = Gi[k][2];
            float G11r = Gr[k][3], G11i = Gi[k][3];
            float fA0r = 2.f * G00r + G11r, fA0i = 2.f * G00i + G11i;
            float fA1r = 2.f * G11r + G00r, fA1i = 2.f * G11i + G00i;
            fwm0r += xs_x * fA0r - xs_y * fA0i;
            fwm0i += xs_x * fA0i + xs_y * fA0r;
            fwm0r += xs_z * G01r - xs_w * G01i;
            fwm0i += xs_z * G01i + xs_w * G01r;
            fwm1r += xs_z * fA1r - xs_w * fA1i;
            fwm1i += xs_z * fA1i + xs_w * fA1r;
            fwm1r += xs_x * G10r - xs_y * G10i;
            fwm1i += xs_x * G10i + xs_y * G10r;
        }

        // ---- assemble ----
        float s0, c0, s1, c1;
        sincosf(phi0, &s0, &c0);
        sincosf(phi1, &s1, &c1);
        float o0r = xc_x * c0 - xc_y * s0 + ici0r + fwm0r;
        float o0i = xc_x * s0 + xc_y * c0 + ici0i + fwm0i;
        float o1r = xc_z * c1 - xc_w * s1 + ici1r + fwm1r;
        float o1i = xc_z * s1 + xc_w * c1 + ici1i + fwm1i;

        float4* outv = (float4*)(out + ((size_t)(b * (size_t)Lout + l)) * 4);
        *outv = make_float4(o0r * rsP, o0i * rsP, o1r * rsP, o1i * rsP);
    }
}

extern "C" void kernel_launch(void* const* d_in, const int* in_sizes, int n_in,
                              void* d_out, int out_size)
{
    const float* x_real    = (const float*)d_in[0];
    const float* x_imag    = (const float*)d_in[1];
    const float* task_info = (const float*)d_in[2];
    const float* C00       = (const float*)d_in[3];
    const float* ixpm_w    = (const float*)d_in[4];
    const float* icixpm_w  = (const float*)d_in[5];
    const float* fwm_wr    = (const float*)d_in[6];
    const float* fwm_wi    = (const float*)d_in[7];

    int B = in_sizes[2] / 4;
    int M = in_sizes[0] / (B * 2);
    int Lout = M - NTAPS + 1;

    cudaFuncSetAttribute(snse_kernel,
                         cudaFuncAttributeMaxDynamicSharedMemorySize, DYNBYTES);

    dim3 grid((Lout + OUTS - 1) / OUTS, B);
    snse_kernel<<<grid, TILE, DYNBYTES>>>(x_real, x_imag, task_info, C00,
                                          ixpm_w, icixpm_w, fwm_wr, fwm_wi,
                                          (float*)d_out, M, Lout);
}

// round 9
// speedup vs baseline: 1.5458x; 1.0715x over previous
#include <cuda_runtime.h>
#include <math.h>

#define NTAPS 201
#define HALF  100
#define NT3   204           // weight rows: taps 0..202 used + zero row 203
#define TILE  128           // threads; each thread computes 2 adjacent outputs
#define OUTS  256           // outputs per block
#define WIN   464           // window entries (need 461)
#define ST2   576           // skewed stride per paired array (max a = 460+115=575)
#define NARR2 5
#define DYNBYTES (NARR2 * ST2 * 16)

typedef unsigned long long ull;

__device__ __forceinline__ ull pk(float lo, float hi) {
    ull r; asm("mov.b64 %0, {%1, %2};" : "=l"(r) : "f"(lo), "f"(hi)); return r;
}
__device__ __forceinline__ float2 upk(ull v) {
    float2 r; asm("mov.b64 {%0, %1}, %2;" : "=f"(r.x), "=f"(r.y) : "l"(v)); return r;
}
__device__ __forceinline__ void fma2(ull &d, ull a, ull b) {
    asm("fma.rn.f32x2 %0, %1, %2, %0;" : "+l"(d) : "l"(a), "l"(b));
}

// Phase 1 precomputes per window position p, packed PAIRWISE for LDS.128:
//   sE[0][a] = { D00+1, D01+1 }   sE[1][a] = { D10+1, D11+1 }   (shift +1)
//   sE[2][a] = { D00+2, D01+2 }   sE[3][a] = { D10+2, D11+2 }   (shift +2)
//   sE[4][a] = { q, ps }          q = X0*conj(X1), ps = (2p0+p1, 2p1+p0)
// skew a = p + (p>>2) in 16-byte units -> exactly 4 wavefronts per LDS.128
// for the hot loop's stride-2-position access (verified even bank spread).
// Phase 2: thread t owns outputs lA = l0+2t and lB = lA+1; one product read
// feeds output A at tap j (weights w[j]) and B at tap j-1 (previous weights).

__global__ __launch_bounds__(TILE, 2)
void snse_kernel(const float* __restrict__ x_real,
                 const float* __restrict__ x_imag,
                 const float* __restrict__ task_info,
                 const float* __restrict__ C00p,
                 const float* __restrict__ ixpm_w,
                 const float* __restrict__ icixpm_w,
                 const float* __restrict__ fwm_wr,
                 const float* __restrict__ fwm_wi,
                 float* __restrict__ out,
                 int M, int Lout)
{
    __shared__ ulonglong2 sU[WIN];
    __shared__ ulonglong2 sW[NT3 * 5];
    extern __shared__ ulonglong2 sE[];     // NARR2 arrays of ST2 ulonglong2

    const int b  = blockIdx.y;
    const int l0 = blockIdx.x * OUTS;
    const int t  = threadIdx.x;

    const float dbm = task_info[b * 4];
    const float P   = exp10f(dbm * 0.1f) * 0.5f;   // /Nm, Nm=2
    const float sP  = sqrtf(P);
    const float rsP = 1.0f / sP;
    const float C00 = C00p[0];

    // ---- build pre-splatted weight table (zero outside valid ranges) ----
    for (int j = t; j < NT3; j += TILE) {
        float wrP1 = (j <= 200) ? fwm_wr[2 * NTAPS + j] : 0.f;
        float wiP1 = (j <= 200) ? fwm_wi[2 * NTAPS + j] : 0.f;
        float wrP2 = (j <= 200) ? fwm_wr[3 * NTAPS + j] : 0.f;
        float wiP2 = (j <= 200) ? fwm_wi[3 * NTAPS + j] : 0.f;
        float wrM1 = (j >= 1 && j <= 201) ? fwm_wr[1 * NTAPS + (j - 1)] : 0.f;
        float wiM1 = (j >= 1 && j <= 201) ? fwm_wi[1 * NTAPS + (j - 1)] : 0.f;
        float wrM2 = (j >= 2 && j <= 202) ? fwm_wr[0 * NTAPS + (j - 2)] : 0.f;
        float wiM2 = (j >= 2 && j <= 202) ? fwm_wi[0 * NTAPS + (j - 2)] : 0.f;
        float wx   = (j <= 200) ? ixpm_w[j]   : 0.f;
        float wq   = (j <= 200) ? icixpm_w[j] : 0.f;
        sW[5 * j + 0] = make_ulonglong2(pk(wrP1, wrP1), pk(wiP1, wiP1));
        sW[5 * j + 1] = make_ulonglong2(pk(wrP2, wrP2), pk(wiP2, wiP2));
        sW[5 * j + 2] = make_ulonglong2(pk(wrM1, wrM1), pk(wiM1, wiM1));
        sW[5 * j + 3] = make_ulonglong2(pk(wrM2, wrM2), pk(wiM2, wiM2));
        sW[5 * j + 4] = make_ulonglong2(pk(wx, wx), pk(wq, wq));
    }

    // ---- load scaled x window with mod-M wrap ----
    const float* xr = x_real + (size_t)b * M * 2;
    const float* xi = x_imag + (size_t)b * M * 2;
    for (int idx = t; idx < WIN; idx += TILE) {
        int g  = l0 - 2 + idx;
        int gm = (g < 0) ? g + M : ((g >= M) ? g - M : g);
        float r0 = xr[gm * 2 + 0] * sP, r1 = xr[gm * 2 + 1] * sP;
        float i0 = xi[gm * 2 + 0] * sP, i1 = xi[gm * 2 + 1] * sP;
        sU[idx] = make_ulonglong2(pk(r0, i0), pk(r1, i1));
    }
    __syncthreads();

    // ---- phase 1: per-position products into skewed paired arrays ----
    for (int idx = t; idx < 459; idx += TILE) {
        int p = idx + 2;
        ulonglong2 u0 = sU[p], u1 = sU[p - 1], u2 = sU[p - 2];
        float2 f0 = upk(u0.x), f1 = upk(u0.y);
        float2 a0 = upk(u1.x), a1 = upk(u1.y);
        float2 b0 = upk(u2.x), b1 = upk(u2.y);
        int a = p + (p >> 2);
        sE[0 * ST2 + a] = make_ulonglong2(
            pk(f0.x * a0.x + f0.y * a0.y, f0.y * a0.x - f0.x * a0.y),
            pk(f0.x * a1.x + f0.y * a1.y, f0.y * a1.x - f0.x * a1.y));
        sE[1 * ST2 + a] = make_ulonglong2(
            pk(f1.x * a0.x + f1.y * a0.y, f1.y * a0.x - f1.x * a0.y),
            pk(f1.x * a1.x + f1.y * a1.y, f1.y * a1.x - f1.x * a1.y));
        sE[2 * ST2 + a] = make_ulonglong2(
            pk(f0.x * b0.x + f0.y * b0.y, f0.y * b0.x - f0.x * b0.y),
            pk(f0.x * b1.x + f0.y * b1.y, f0.y * b1.x - f0.x * b1.y));
        sE[3 * ST2 + a] = make_ulonglong2(
            pk(f1.x * b0.x + f1.y * b0.y, f1.y * b0.x - f1.x * b0.y),
            pk(f1.x * b1.x + f1.y * b1.y, f1.y * b1.x - f1.x * b1.y));
        float p0 = f0.x * f0.x + f0.y * f0.y;
        float p1 = f1.x * f1.x + f1.y * f1.y;
        sE[4 * ST2 + a] = make_ulonglong2(
            pk(f0.x * f1.x + f0.y * f1.y, f0.y * f1.x - f0.x * f1.y),
            pk(2.f * p0 + p1, 2.f * p1 + p0));
    }
    __syncthreads();

    const int base = 2 * t;        // window index of output A's position l
    const int lA = l0 + base;

    // ---- accumulators for BOTH outputs ----
    ull ApA[8], BpA[8], AmA[8], BmA[8];
    ull ApB[8], BpB[8], AmB[8], BmB[8];
#pragma unroll
    for (int k = 0; k < 8; ++k) {
        ApA[k] = BpA[k] = AmA[k] = BmA[k] = 0ULL;
        ApB[k] = BpB[k] = AmB[k] = BmB[k] = 0ULL;
    }
    ull axpA = 0ULL, axpB = 0ULL;  // (axp0, axp1) per output
    ull qcA  = 0ULL, qcB  = 0ULL;  // (qcr, qci) per output

    // previous-iteration weights (tap j-1 for output B); zero at j=0
    ull pA0 = 0, pA1 = 0, pB0 = 0, pB1 = 0, pC0 = 0, pC1 = 0, pD0 = 0, pD1 = 0;
    ull pE0 = 0, pE1 = 0;

#pragma unroll 2
    for (int j = 0; j < NT3; ++j) {
        const int e = base + 2 + j;
        const int a = e + (e >> 2);
        ulonglong2 e0 = sE[0 * ST2 + a];
        ulonglong2 e1 = sE[1 * ST2 + a];
        ulonglong2 e2 = sE[2 * ST2 + a];
        ulonglong2 e3 = sE[3 * ST2 + a];
        ulonglong2 e4 = sE[4 * ST2 + a];
        ull d0 = e0.x, d1 = e0.y, d2 = e1.x, d3 = e1.y;
        ull d4 = e2.x, d5 = e2.y, d6 = e3.x, d7 = e3.y;
        ull qd = e4.x, ps = e4.y;
        ulonglong2 wA = sW[5 * j + 0];
        ulonglong2 wB = sW[5 * j + 1];
        ulonglong2 wC = sW[5 * j + 2];
        ulonglong2 wD = sW[5 * j + 3];
        ulonglong2 wE = sW[5 * j + 4];

        fma2(axpA, ps, wE.x);  fma2(axpB, ps, pE0);
        fma2(qcA,  qd, wE.y);  fma2(qcB,  qd, pE1);

        // shift +1 products
        fma2(ApA[0], d0, wA.x); fma2(BpA[0], d0, wA.y);
        fma2(AmA[0], d0, wC.x); fma2(BmA[0], d0, wC.y);
        fma2(ApB[0], d0, pA0);  fma2(BpB[0], d0, pA1);
        fma2(AmB[0], d0, pC0);  fma2(BmB[0], d0, pC1);

        fma2(ApA[1], d1, wA.x); fma2(BpA[1], d1, wA.y);
        fma2(AmA[1], d1, wC.x); fma2(BmA[1], d1, wC.y);
        fma2(ApB[1], d1, pA0);  fma2(BpB[1], d1, pA1);
        fma2(AmB[1], d1, pC0);  fma2(BmB[1], d1, pC1);

        fma2(ApA[2], d2, wA.x); fma2(BpA[2], d2, wA.y);
        fma2(AmA[2], d2, wC.x); fma2(BmA[2], d2, wC.y);
        fma2(ApB[2], d2, pA0);  fma2(BpB[2], d2, pA1);
        fma2(AmB[2], d2, pC0);  fma2(BmB[2], d2, pC1);

        fma2(ApA[3], d3, wA.x); fma2(BpA[3], d3, wA.y);
        fma2(AmA[3], d3, wC.x); fma2(BmA[3], d3, wC.y);
        fma2(ApB[3], d3, pA0);  fma2(BpB[3], d3, pA1);
        fma2(AmB[3], d3, pC0);  fma2(BmB[3], d3, pC1);

        // shift +2 products
        fma2(ApA[4], d4, wB.x); fma2(BpA[4], d4, wB.y);
        fma2(AmA[4], d4, wD.x); fma2(BmA[4], d4, wD.y);
        fma2(ApB[4], d4, pB0);  fma2(BpB[4], d4, pB1);
        fma2(AmB[4], d4, pD0);  fma2(BmB[4], d4, pD1);

        fma2(ApA[5], d5, wB.x); fma2(BpA[5], d5, wB.y);
        fma2(AmA[5], d5, wD.x); fma2(BmA[5], d5, wD.y);
        fma2(ApB[5], d5, pB0);  fma2(BpB[5], d5, pB1);
        fma2(AmB[5], d5, pD0);  fma2(BmB[5], d5, pD1);

        fma2(ApA[6], d6, wB.x); fma2(BpA[6], d6, wB.y);
        fma2(AmA[6], d6, wD.x); fma2(BmA[6], d6, wD.y);
        fma2(ApB[6], d6, pB0);  fma2(BpB[6], d6, pB1);
        fma2(AmB[6], d6, pD0);  fma2(BmB[6], d6, pD1);

        fma2(ApA[7], d7, wB.x); fma2(BpA[7], d7, wB.y);
        fma2(AmA[7], d7, wD.x); fma2(BmA[7], d7, wD.y);
        fma2(ApB[7], d7, pB0);  fma2(BpB[7], d7, pB1);
        fma2(AmB[7], d7, pD0);  fma2(BmB[7], d7, pD1);

        // weight history (renamed away by unroll 2)
        pA0 = wA.x; pA1 = wA.y; pB0 = wB.x; pB1 = wB.y;
        pC0 = wC.x; pC1 = wC.y; pD0 = wD.x; pD1 = wD.y;
        pE0 = wE.x; pE1 = wE.y;
    }

    const float wxc = ixpm_w[HALF];
    const float wqc = icixpm_w[HALF];

#pragma unroll
    for (int o = 0; o < 2; ++o) {
        const int l = lA + o;
        if (l >= Lout) break;
        const int bi = base + o;
        const ull* Ap = o ? ApB : ApA;
        const ull* Bp = o ? BpB : BpA;
        const ull* Am = o ? AmB : AmA;
        const ull* Bm = o ? BmB : BmA;
        float2 axpf = upk(o ? axpB : axpA);
        float2 qcf  = upk(o ? qcB  : qcA);
        float axp0 = axpf.x, axp1 = axpf.y;
        float qcr = qcf.x, qci = qcf.y;

        // ---- center position ----
        ulonglong2 xcu = sU[bi + 102];
        float2 x0 = upk(xcu.x), x1 = upk(xcu.y);
        float xc_x = x0.x, xc_y = x0.y, xc_z = x1.x, xc_w = x1.y;

        // ---- center-tap corrections ----
        float pc0 = xc_x * xc_x + xc_y * xc_y;
        float pc1 = xc_z * xc_z + xc_w * xc_w;
        axp0 -= wxc * (2.f * pc0 + pc1);
        axp1 -= wxc * (2.f * pc1 + pc0);
        qcr -= wqc * (xc_x * xc_z + xc_y * xc_w);
        qci -= wqc * (xc_y * xc_z - xc_x * xc_w);

        float spm  = C00 * (pc0 + pc1);
        float phi0 = spm + 2.f * axp0;
        float phi1 = spm + 2.f * axp1;

        // ---- ici ----
        float ici0r = -(xc_z * qci + xc_w * qcr);
        float ici0i =   xc_z * qcr - xc_w * qci;
        float ici1r =   xc_x * qci - xc_y * qcr;
        float ici1i =   xc_x * qcr + xc_y * qci;

        // ---- recombine G (k=0..3 <-> s=-2,-1,1,2) ----
        float Gr[4][4], Gi[4][4];
        const int sw[4] = {0, 2, 1, 3};
#pragma unroll
        for (int m = 0; m < 4; ++m) {
            float2 a, bb;
            a = upk(Ap[m]); bb = upk(Bp[m]);
            Gr[2][m] = a.x - bb.y;  Gi[2][m] = a.y + bb.x;
            a = upk(Ap[4 + m]); bb = upk(Bp[4 + m]);
            Gr[3][m] = a.x - bb.y;  Gi[3][m] = a.y + bb.x;
            a = upk(Am[sw[m]]); bb = upk(Bm[sw[m]]);
            Gr[1][m] = a.x + bb.y;  Gi[1][m] = bb.x - a.y;
            a = upk(Am[4 + sw[m]]); bb = upk(Bm[4 + sw[m]]);
            Gr[0][m] = a.x + bb.y;  Gi[0][m] = bb.x - a.y;
        }

        // ---- FWM combine ----
        float fwm0r = 0.f, fwm0i = 0.f, fwm1r = 0.f, fwm1i = 0.f;
        const int soff[4] = {104, 103, 101, 100};
#pragma unroll
        for (int k = 0; k < 4; ++k) {
            ulonglong2 xsu = sU[bi + soff[k]];
            float2 s0f = upk(xsu.x), s1f = upk(xsu.y);
            float xs_x = s0f.x, xs_y = s0f.y, xs_z = s1f.x, xs_w = s1f.y;
            float G00r = Gr[k][0], G00i = Gi[k][0];
            float G01r = Gr[k][1], G01i = Gi[k][1];
            float G10r = Gr[k][2], G10i = Gi[k][2];
            float G11r = Gr[k][3], G11i = Gi[k][3];
            float fA0r = 2.f * G00r + G11r, fA0i = 2.f * G00i + G11i;
            float fA1r = 2.f * G11r + G00r, fA1i = 2.f * G11i + G00i;
            fwm0r += xs_x * fA0r - xs_y * fA0i;
            fwm0i += xs_x * fA0i + xs_y * fA0r;
            fwm0r += xs_z * G01r - xs_w * G01i;
            fwm0i += xs_z * G01i + xs_w * G01r;
            fwm1r += xs_z * fA1r - xs_w * fA1i;
            fwm1i += xs_z * fA1i + xs_w * fA1r;
            fwm1r += xs_x * G10r - xs_y * G10i;
            fwm1i += xs_x * G10i + xs_y * G10r;
        }

        // ---- assemble ----
        float s0, c0, s1, c1;
        sincosf(phi0, &s0, &c0);
        sincosf(phi1, &s1, &c1);
        float o0r = xc_x * c0 - xc_y * s0 + ici0r + fwm0r;
        float o0i = xc_x * s0 + xc_y * c0 + ici0i + fwm0i;
        float o1r = xc_z * c1 - xc_w * s1 + ici1r + fwm1r;
        float o1i = xc_z * s1 + xc_w * c1 + ici1i + fwm1i;

        float4* outv = (float4*)(out + ((size_t)(b * (size_t)Lout + l)) * 4);
        *outv = make_float4(o0r * rsP, o0i * rsP, o1r * rsP, o1i * rsP);
    }
}

extern "C" void kernel_launch(void* const* d_in, const int* in_sizes, int n_in,
                              void* d_out, int out_size)
{
    const float* x_real    = (const float*)d_in[0];
    const float* x_imag    = (const float*)d_in[1];
    const float* task_info = (const float*)d_in[2];
    const float* C00       = (const float*)d_in[3];
    const float* ixpm_w    = (const float*)d_in[4];
    const float* icixpm_w  = (const float*)d_in[5];
    const float* fwm_wr    = (const float*)d_in[6];
    const float* fwm_wi    = (const float*)d_in[7];

    int B = in_sizes[2] / 4;
    int M = in_sizes[0] / (B * 2);
    int Lout = M - NTAPS + 1;

    cudaFuncSetAttribute(snse_kernel,
                         cudaFuncAttributeMaxDynamicSharedMemorySize, DYNBYTES);

    dim3 grid((Lout + OUTS - 1) / OUTS, B);
    snse_kernel<<<grid, TILE, DYNBYTES>>>(x_real, x_imag, task_info, C00,
                                          ixpm_w, icixpm_w, fwm_wr, fwm_wi,
                                          (float*)d_out, M, Lout);
}

// round 10
// speedup vs baseline: 1.6770x; 1.0849x over previous
#include <cuda_runtime.h>
#include <math.h>

#define NTAPS 201
#define HALF  100
#define NT3   204           // taps 0..202 used + zero row 203; 204 = 2*102
#define TILE  128           // threads; each thread computes 2 adjacent outputs
#define OUTS  256           // outputs per block
#define WIN   464           // window entries (need 461)
#define STP   233           // per-array stride (ulonglong2 units), odd to de-conflict
#define DYNBYTES (10 * STP * 16)

typedef unsigned long long ull;

__device__ __forceinline__ ull pk(float lo, float hi) {
    ull r; asm("mov.b64 %0, {%1, %2};" : "=l"(r) : "f"(lo), "f"(hi)); return r;
}
__device__ __forceinline__ float2 upk(ull v) {
    float2 r; asm("mov.b64 {%0, %1}, %2;" : "=f"(r.x), "=f"(r.y) : "l"(v)); return r;
}
__device__ __forceinline__ void fma2(ull &d, ull a, ull b) {
    asm("fma.rn.f32x2 %0, %1, %2, %0;" : "+l"(d) : "l"(a), "l"(b));
}

// Phase 1 precomputes per window position p, split by PARITY of p:
//   arrays 0..4 (even p) / 5..9 (odd p), indexed by p>>1:
//   arr0 = { D00+1, D01+1 }  arr1 = { D10+1, D11+1 }   (shift +1 products)
//   arr2 = { D00+2, D01+2 }  arr3 = { D10+2, D11+2 }   (shift +2 products)
//   arr4 = { q, ps }   q = X0*conj(X1), ps = (2p0+p1, 2p1+p0)
// At tap j all lanes read the SAME parity array at CONSECUTIVE indices
// t+1+j/2 -> perfectly coalesced LDS.128 (4 wavefronts, no conflicts).
// Phase 2: thread t owns outputs lA = l0+2t and lB = lA+1; each product read
// feeds A at tap j (weights w[j]) and B at tap j-1 (previous tap's weights).

// accumulate one tap: products E0..E4, current weights WA..WE (output A),
// previous-tap weights PA..PE (output B)
#define ACC_TAP(E0,E1,E2,E3,E4, WA,WB,WC,WD,WE, PA,PB,PC,PD,PE) do {          \
    ull d0=(E0).x, d1=(E0).y, d2=(E1).x, d3=(E1).y;                           \
    ull d4=(E2).x, d5=(E2).y, d6=(E3).x, d7=(E3).y;                           \
    ull qd=(E4).x, ps=(E4).y;                                                 \
    fma2(axpA, ps, (WE).x);  fma2(axpB, ps, (PE).x);                          \
    fma2(qcA,  qd, (WE).y);  fma2(qcB,  qd, (PE).y);                          \
    fma2(ApA[0], d0, (WA).x); fma2(BpA[0], d0, (WA).y);                       \
    fma2(AmA[0], d0, (WC).x); fma2(BmA[0], d0, (WC).y);                       \
    fma2(ApB[0], d0, (PA).x); fma2(BpB[0], d0, (PA).y);                       \
    fma2(AmB[0], d0, (PC).x); fma2(BmB[0], d0, (PC).y);                       \
    fma2(ApA[1], d1, (WA).x); fma2(BpA[1], d1, (WA).y);                       \
    fma2(AmA[1], d1, (WC).x); fma2(BmA[1], d1, (WC).y);                       \
    fma2(ApB[1], d1, (PA).x); fma2(BpB[1], d1, (PA).y);                       \
    fma2(AmB[1], d1, (PC).x); fma2(BmB[1], d1, (PC).y);                       \
    fma2(ApA[2], d2, (WA).x); fma2(BpA[2], d2, (WA).y);                       \
    fma2(AmA[2], d2, (WC).x); fma2(BmA[2], d2, (WC).y);                       \
    fma2(ApB[2], d2, (PA).x); fma2(BpB[2], d2, (PA).y);                       \
    fma2(AmB[2], d2, (PC).x); fma2(BmB[2], d2, (PC).y);                       \
    fma2(ApA[3], d3, (WA).x); fma2(BpA[3], d3, (WA).y);                       \
    fma2(AmA[3], d3, (WC).x); fma2(BmA[3], d3, (WC).y);                       \
    fma2(ApB[3], d3, (PA).x); fma2(BpB[3], d3, (PA).y);                       \
    fma2(AmB[3], d3, (PC).x); fma2(BmB[3], d3, (PC).y);                       \
    fma2(ApA[4], d4, (WB).x); fma2(BpA[4], d4, (WB).y);                       \
    fma2(AmA[4], d4, (WD).x); fma2(BmA[4], d4, (WD).y);                       \
    fma2(ApB[4], d4, (PB).x); fma2(BpB[4], d4, (PB).y);                       \
    fma2(AmB[4], d4, (PD).x); fma2(BmB[4], d4, (PD).y);                       \
    fma2(ApA[5], d5, (WB).x); fma2(BpA[5], d5, (WB).y);                       \
    fma2(AmA[5], d5, (WD).x); fma2(BmA[5], d5, (WD).y);                       \
    fma2(ApB[5], d5, (PB).x); fma2(BpB[5], d5, (PB).y);                       \
    fma2(AmB[5], d5, (PD).x); fma2(BmB[5], d5, (PD).y);                       \
    fma2(ApA[6], d6, (WB).x); fma2(BpA[6], d6, (WB).y);                       \
    fma2(AmA[6], d6, (WD).x); fma2(BmA[6], d6, (WD).y);                       \
    fma2(ApB[6], d6, (PB).x); fma2(BpB[6], d6, (PB).y);                       \
    fma2(AmB[6], d6, (PD).x); fma2(BmB[6], d6, (PD).y);                       \
    fma2(ApA[7], d7, (WB).x); fma2(BpA[7], d7, (WB).y);                       \
    fma2(AmA[7], d7, (WD).x); fma2(BmA[7], d7, (WD).y);                       \
    fma2(ApB[7], d7, (PB).x); fma2(BpB[7], d7, (PB).y);                       \
    fma2(AmB[7], d7, (PD).x); fma2(BmB[7], d7, (PD).y);                       \
} while (0)

__global__ __launch_bounds__(TILE, 2)
void snse_kernel(const float* __restrict__ x_real,
                 const float* __restrict__ x_imag,
                 const float* __restrict__ task_info,
                 const float* __restrict__ C00p,
                 const float* __restrict__ ixpm_w,
                 const float* __restrict__ icixpm_w,
                 const float* __restrict__ fwm_wr,
                 const float* __restrict__ fwm_wi,
                 float* __restrict__ out,
                 int M, int Lout)
{
    __shared__ ulonglong2 sU[WIN];
    __shared__ ulonglong2 sW[NT3 * 5];
    extern __shared__ ulonglong2 sD[];     // 10 arrays of STP ulonglong2

    const int b  = blockIdx.y;
    const int l0 = blockIdx.x * OUTS;
    const int t  = threadIdx.x;

    const float dbm = task_info[b * 4];
    const float P   = exp10f(dbm * 0.1f) * 0.5f;   // /Nm, Nm=2
    const float sP  = sqrtf(P);
    const float rsP = 1.0f / sP;
    const float C00 = C00p[0];

    // ---- build pre-splatted weight table (zero outside valid ranges) ----
    for (int j = t; j < NT3; j += TILE) {
        float wrP1 = (j <= 200) ? fwm_wr[2 * NTAPS + j] : 0.f;
        float wiP1 = (j <= 200) ? fwm_wi[2 * NTAPS + j] : 0.f;
        float wrP2 = (j <= 200) ? fwm_wr[3 * NTAPS + j] : 0.f;
        float wiP2 = (j <= 200) ? fwm_wi[3 * NTAPS + j] : 0.f;
        float wrM1 = (j >= 1 && j <= 201) ? fwm_wr[1 * NTAPS + (j - 1)] : 0.f;
        float wiM1 = (j >= 1 && j <= 201) ? fwm_wi[1 * NTAPS + (j - 1)] : 0.f;
        float wrM2 = (j >= 2 && j <= 202) ? fwm_wr[0 * NTAPS + (j - 2)] : 0.f;
        float wiM2 = (j >= 2 && j <= 202) ? fwm_wi[0 * NTAPS + (j - 2)] : 0.f;
        float wx   = (j <= 200) ? ixpm_w[j]   : 0.f;
        float wq   = (j <= 200) ? icixpm_w[j] : 0.f;
        sW[5 * j + 0] = make_ulonglong2(pk(wrP1, wrP1), pk(wiP1, wiP1));
        sW[5 * j + 1] = make_ulonglong2(pk(wrP2, wrP2), pk(wiP2, wiP2));
        sW[5 * j + 2] = make_ulonglong2(pk(wrM1, wrM1), pk(wiM1, wiM1));
        sW[5 * j + 3] = make_ulonglong2(pk(wrM2, wrM2), pk(wiM2, wiM2));
        sW[5 * j + 4] = make_ulonglong2(pk(wx, wx), pk(wq, wq));
    }

    // ---- load scaled x window with mod-M wrap ----
    const float* xr = x_real + (size_t)b * M * 2;
    const float* xi = x_imag + (size_t)b * M * 2;
    for (int idx = t; idx < WIN; idx += TILE) {
        int g  = l0 - 2 + idx;
        int gm = (g < 0) ? g + M : ((g >= M) ? g - M : g);
        float r0 = xr[gm * 2 + 0] * sP, r1 = xr[gm * 2 + 1] * sP;
        float i0 = xi[gm * 2 + 0] * sP, i1 = xi[gm * 2 + 1] * sP;
        sU[idx] = make_ulonglong2(pk(r0, i0), pk(r1, i1));
    }
    __syncthreads();

    // ---- phase 1: per-position products into parity-split arrays ----
    for (int idx = t; idx < 459; idx += TILE) {
        int p = idx + 2;
        ulonglong2 u0 = sU[p], u1 = sU[p - 1], u2 = sU[p - 2];
        float2 f0 = upk(u0.x), f1 = upk(u0.y);
        float2 a0 = upk(u1.x), a1 = upk(u1.y);
        float2 b0 = upk(u2.x), b1 = upk(u2.y);
        int po = (p & 1) * 5;          // parity array group
        int ix = p >> 1;
        sD[(po + 0) * STP + ix] = make_ulonglong2(
            pk(f0.x * a0.x + f0.y * a0.y, f0.y * a0.x - f0.x * a0.y),
            pk(f0.x * a1.x + f0.y * a1.y, f0.y * a1.x - f0.x * a1.y));
        sD[(po + 1) * STP + ix] = make_ulonglong2(
            pk(f1.x * a0.x + f1.y * a0.y, f1.y * a0.x - f1.x * a0.y),
            pk(f1.x * a1.x + f1.y * a1.y, f1.y * a1.x - f1.x * a1.y));
        sD[(po + 2) * STP + ix] = make_ulonglong2(
            pk(f0.x * b0.x + f0.y * b0.y, f0.y * b0.x - f0.x * b0.y),
            pk(f0.x * b1.x + f0.y * b1.y, f0.y * b1.x - f0.x * b1.y));
        sD[(po + 3) * STP + ix] = make_ulonglong2(
            pk(f1.x * b0.x + f1.y * b0.y, f1.y * b0.x - f1.x * b0.y),
            pk(f1.x * b1.x + f1.y * b1.y, f1.y * b1.x - f1.x * b1.y));
        float p0 = f0.x * f0.x + f0.y * f0.y;
        float p1 = f1.x * f1.x + f1.y * f1.y;
        sD[(po + 4) * STP + ix] = make_ulonglong2(
            pk(f0.x * f1.x + f0.y * f1.y, f0.y * f1.x - f0.x * f1.y),
            pk(2.f * p0 + p1, 2.f * p1 + p0));
    }
    __syncthreads();

    const int base = 2 * t;        // window index of output A's position l
    const int lA = l0 + base;

    // ---- accumulators for BOTH outputs ----
    ull ApA[8], BpA[8], AmA[8], BmA[8];
    ull ApB[8], BpB[8], AmB[8], BmB[8];
#pragma unroll
    for (int k = 0; k < 8; ++k) {
        ApA[k] = BpA[k] = AmA[k] = BmA[k] = 0ULL;
        ApB[k] = BpB[k] = AmB[k] = BmB[k] = 0ULL;
    }
    ull axpA = 0ULL, axpB = 0ULL;  // (axp0, axp1) per output
    ull qcA  = 0ULL, qcB  = 0ULL;  // (qcr, qci) per output

    // previous-tap weights (for output B); zero before tap 0
    ulonglong2 z2 = make_ulonglong2(0ULL, 0ULL);
    ulonglong2 pA = z2, pB = z2, pC = z2, pD = z2, pE = z2;

    // taps processed in parity pairs: j=2k reads even array, j=2k+1 odd array,
    // both at index t+1+k (consecutive across lanes -> coalesced LDS.128)
#pragma unroll 2
    for (int k = 0; k < NT3 / 2; ++k) {
        const int ix = t + 1 + k;
        // even tap j = 2k
        ulonglong2 e0 = sD[0 * STP + ix];
        ulonglong2 e1 = sD[1 * STP + ix];
        ulonglong2 e2 = sD[2 * STP + ix];
        ulonglong2 e3 = sD[3 * STP + ix];
        ulonglong2 e4 = sD[4 * STP + ix];
        ulonglong2 wA = sW[10 * k + 0];
        ulonglong2 wB = sW[10 * k + 1];
        ulonglong2 wC = sW[10 * k + 2];
        ulonglong2 wD = sW[10 * k + 3];
        ulonglong2 wE = sW[10 * k + 4];
        ACC_TAP(e0, e1, e2, e3, e4, wA, wB, wC, wD, wE, pA, pB, pC, pD, pE);

        // odd tap j = 2k+1 (B side uses even tap's weights)
        ulonglong2 o0 = sD[5 * STP + ix];
        ulonglong2 o1 = sD[6 * STP + ix];
        ulonglong2 o2 = sD[7 * STP + ix];
        ulonglong2 o3 = sD[8 * STP + ix];
        ulonglong2 o4 = sD[9 * STP + ix];
        ulonglong2 vA = sW[10 * k + 5];
        ulonglong2 vB = sW[10 * k + 6];
        ulonglong2 vC = sW[10 * k + 7];
        ulonglong2 vD = sW[10 * k + 8];
        ulonglong2 vE = sW[10 * k + 9];
        ACC_TAP(o0, o1, o2, o3, o4, vA, vB, vC, vD, vE, wA, wB, wC, wD, wE);

        // carry odd weights to next pair's even tap (renamed by unroll 2)
        pA = vA; pB = vB; pC = vC; pD = vD; pE = vE;
    }

    const float wxc = ixpm_w[HALF];
    const float wqc = icixpm_w[HALF];

#pragma unroll
    for (int o = 0; o < 2; ++o) {
        const int l = lA + o;
        if (l >= Lout) break;
        const int bi = base + o;
        const ull* Ap = o ? ApB : ApA;
        const ull* Bp = o ? BpB : BpA;
        const ull* Am = o ? AmB : AmA;
        const ull* Bm = o ? BmB : BmA;
        float2 axpf = upk(o ? axpB : axpA);
        float2 qcf  = upk(o ? qcB  : qcA);
        float axp0 = axpf.x, axp1 = axpf.y;
        float qcr = qcf.x, qci = qcf.y;

        // ---- center position ----
        ulonglong2 xcu = sU[bi + 102];
        float2 x0 = upk(xcu.x), x1 = upk(xcu.y);
        float xc_x = x0.x, xc_y = x0.y, xc_z = x1.x, xc_w = x1.y;

        // ---- center-tap corrections ----
        float pc0 = xc_x * xc_x + xc_y * xc_y;
        float pc1 = xc_z * xc_z + xc_w * xc_w;
        axp0 -= wxc * (2.f * pc0 + pc1);
        axp1 -= wxc * (2.f * pc1 + pc0);
        qcr -= wqc * (xc_x * xc_z + xc_y * xc_w);
        qci -= wqc * (xc_y * xc_z - xc_x * xc_w);

        float spm  = C00 * (pc0 + pc1);
        float phi0 = spm + 2.f * axp0;
        float phi1 = spm + 2.f * axp1;

        // ---- ici ----
        float ici0r = -(xc_z * qci + xc_w * qcr);
        float ici0i =   xc_z * qcr - xc_w * qci;
        float ici1r =   xc_x * qci - xc_y * qcr;
        float ici1i =   xc_x * qcr + xc_y * qci;

        // ---- recombine G (k=0..3 <-> s=-2,-1,1,2) ----
        float Gr[4][4], Gi[4][4];
        const int sw[4] = {0, 2, 1, 3};
#pragma unroll
        for (int m = 0; m < 4; ++m) {
            float2 a, bb;
            a = upk(Ap[m]); bb = upk(Bp[m]);
            Gr[2][m] = a.x - bb.y;  Gi[2][m] = a.y + bb.x;
            a = upk(Ap[4 + m]); bb = upk(Bp[4 + m]);
            Gr[3][m] = a.x - bb.y;  Gi[3][m] = a.y + bb.x;
            a = upk(Am[sw[m]]); bb = upk(Bm[sw[m]]);
            Gr[1][m] = a.x + bb.y;  Gi[1][m] = bb.x - a.y;
            a = upk(Am[4 + sw[m]]); bb = upk(Bm[4 + sw[m]]);
            Gr[0][m] = a.x + bb.y;  Gi[0][m] = bb.x - a.y;
        }

        // ---- FWM combine ----
        float fwm0r = 0.f, fwm0i = 0.f, fwm1r = 0.f, fwm1i = 0.f;
        const int soff[4] = {104, 103, 101, 100};
#pragma unroll
        for (int k = 0; k < 4; ++k) {
            ulonglong2 xsu = sU[bi + soff[k]];
            float2 s0f = upk(xsu.x), s1f = upk(xsu.y);
            float xs_x = s0f.x, xs_y = s0f.y, xs_z = s1f.x, xs_w = s1f.y;
            float G00r = Gr[k][0], G00i = Gi[k][0];
            float G01r = Gr[k][1], G01i = Gi[k][1];
            float G10r = Gr[k][2], G10i = Gi[k][2];
            float G11r = Gr[k][3], G11i = Gi[k][3];
            float fA0r = 2.f * G00r + G11r, fA0i = 2.f * G00i + G11i;
            float fA1r = 2.f * G11r + G00r, fA1i = 2.f * G11i + G00i;
            fwm0r += xs_x * fA0r - xs_y * fA0i;
            fwm0i += xs_x * fA0i + xs_y * fA0r;
            fwm0r += xs_z * G01r - xs_w * G01i;
            fwm0i += xs_z * G01i + xs_w * G01r;
            fwm1r += xs_z * fA1r - xs_w * fA1i;
            fwm1i += xs_z * fA1i + xs_w * fA1r;
            fwm1r += xs_x * G10r - xs_y * G10i;
            fwm1i += xs_x * G10i + xs_y * G10r;
        }

        // ---- assemble ----
        float s0, c0, s1, c1;
        sincosf(phi0, &s0, &c0);
        sincosf(phi1, &s1, &c1);
        float o0r = xc_x * c0 - xc_y * s0 + ici0r + fwm0r;
        float o0i = xc_x * s0 + xc_y * c0 + ici0i + fwm0i;
        float o1r = xc_z * c1 - xc_w * s1 + ici1r + fwm1r;
        float o1i = xc_z * s1 + xc_w * c1 + ici1i + fwm1i;

        float4* outv = (float4*)(out + ((size_t)(b * (size_t)Lout + l)) * 4);
        *outv = make_float4(o0r * rsP, o0i * rsP, o1r * rsP, o1i * rsP);
    }
}

extern "C" void kernel_launch(void* const* d_in, const int* in_sizes, int n_in,
                              void* d_out, int out_size)
{
    const float* x_real    = (const float*)d_in[0];
    const float* x_imag    = (const float*)d_in[1];
    const float* task_info = (const float*)d_in[2];
    const float* C00       = (const float*)d_in[3];
    const float* ixpm_w    = (const float*)d_in[4];
    const float* icixpm_w  = (const float*)d_in[5];
    const float* fwm_wr    = (const float*)d_in[6];
    const float* fwm_wi    = (const float*)d_in[7];

    int B = in_sizes[2] / 4;
    int M = in_sizes[0] / (B * 2);
    int Lout = M - NTAPS + 1;

    cudaFuncSetAttribute(snse_kernel,
                         cudaFuncAttributeMaxDynamicSharedMemorySize, DYNBYTES);

    dim3 grid((Lout + OUTS - 1) / OUTS, B);
    snse_kernel<<<grid, TILE, DYNBYTES>>>(x_real, x_imag, task_info, C00,
                                          ixpm_w, icixpm_w, fwm_wr, fwm_wi,
                                          (float*)d_out, M, Lout);
}

// round 11
// speedup vs baseline: 1.6799x; 1.0018x over previous
#include <cuda_runtime.h>
#include <math.h>

#define NTAPS 201
#define HALF  100
#define NT3   204           // taps 0..202 used + zero row 203; 204 = 2*102
#define TILE  128           // threads; lane PAIRS share 2 adjacent outputs
#define OUTS  128           // outputs per block
#define WIN   336           // window entries (need 332)
#define STP   170           // per-array stride (ulonglong2); STP%4==2 -> pair chunks 16 banks apart
#define DYNBYTES (10 * STP * 16)

typedef unsigned long long ull;

__device__ __forceinline__ ull pk(float lo, float hi) {
    ull r; asm("mov.b64 %0, {%1, %2};" : "=l"(r) : "f"(lo), "f"(hi)); return r;
}
__device__ __forceinline__ float2 upk(ull v) {
    float2 r; asm("mov.b64 {%0, %1}, %2;" : "=f"(r.x), "=f"(r.y) : "l"(v)); return r;
}
__device__ __forceinline__ void fma2(ull &d, ull a, ull b) {
    asm("fma.rn.f32x2 %0, %1, %2, %0;" : "+l"(d) : "l"(a), "l"(b));
}

// Filter split across lane pairs (2q, 2q+1), both owning outputs lA=l0+2q, lB=lA+1:
//   side 0: +1/-1 shift filters (products d00..d11 of shift+1) + icixpm scalar
//   side 1: +2/-2 shift filters (shift+2 products)            + ixpm scalar
// Product arrays (parity-split by position p as in R10): arrays 0..4 even p,
// 5..9 odd p, index p>>1:
//   arr 2s   = { D00, D01 }  arr 2s+1 = { D10, D11 }   for shift s+1
//   arr 4    = { q, ps }
// Weight rows, 6 per tap j: row s = w(+(s+1)) splat pair {(wr,wr),(wi,wi)},
// row 2+s = w(-(s+1)) (shifted per conj-symmetry), row 4+s = scalar splat.
// Per tap each thread: 4 products x 4 accums x 2 outputs + 2 scalar = 34 fma2.
// Output B uses previous tap's weights (registers, renamed by unroll).
// Epilogue: per-side partials exchanged with one shfl_xor(1); side s stores
// output lA+s (coalesced float4 stores).

#define ACC(E0,E1,SC, WP,WM,WS, PP,PM,PS) do {                                \
    ull d0=(E0).x, d1=(E0).y, d2=(E1).x, d3=(E1).y;                           \
    fma2(scA, (SC), (WS)); fma2(scB, (SC), (PS));                             \
    fma2(GpA[0],d0,(WP).x); fma2(GqA[0],d0,(WP).y);                           \
    fma2(GmA[0],d0,(WM).x); fma2(GnA[0],d0,(WM).y);                           \
    fma2(GpB[0],d0,(PP).x); fma2(GqB[0],d0,(PP).y);                           \
    fma2(GmB[0],d0,(PM).x); fma2(GnB[0],d0,(PM).y);                           \
    fma2(GpA[1],d1,(WP).x); fma2(GqA[1],d1,(WP).y);                           \
    fma2(GmA[1],d1,(WM).x); fma2(GnA[1],d1,(WM).y);                           \
    fma2(GpB[1],d1,(PP).x); fma2(GqB[1],d1,(PP).y);                           \
    fma2(GmB[1],d1,(PM).x); fma2(GnB[1],d1,(PM).y);                           \
    fma2(GpA[2],d2,(WP).x); fma2(GqA[2],d2,(WP).y);                           \
    fma2(GmA[2],d2,(WM).x); fma2(GnA[2],d2,(WM).y);                           \
    fma2(GpB[2],d2,(PP).x); fma2(GqB[2],d2,(PP).y);                           \
    fma2(GmB[2],d2,(PM).x); fma2(GnB[2],d2,(PM).y);                           \
    fma2(GpA[3],d3,(WP).x); fma2(GqA[3],d3,(WP).y);                           \
    fma2(GmA[3],d3,(WM).x); fma2(GnA[3],d3,(WM).y);                           \
    fma2(GpB[3],d3,(PP).x); fma2(GqB[3],d3,(PP).y);                           \
    fma2(GmB[3],d3,(PM).x); fma2(GnB[3],d3,(PM).y);                           \
} while (0)

__global__ __launch_bounds__(TILE, 3)
void snse_kernel(const float* __restrict__ x_real,
                 const float* __restrict__ x_imag,
                 const float* __restrict__ task_info,
                 const float* __restrict__ C00p,
                 const float* __restrict__ ixpm_w,
                 const float* __restrict__ icixpm_w,
                 const float* __restrict__ fwm_wr,
                 const float* __restrict__ fwm_wi,
                 float* __restrict__ out,
                 int M, int Lout)
{
    __shared__ ulonglong2 sU[WIN];
    __shared__ ulonglong2 sW6[NT3 * 6];
    extern __shared__ ulonglong2 sD[];     // 10 arrays of STP ulonglong2

    const int b  = blockIdx.y;
    const int l0 = blockIdx.x * OUTS;
    const int t  = threadIdx.x;

    const float dbm = task_info[b * 4];
    const float P   = exp10f(dbm * 0.1f) * 0.5f;   // /Nm, Nm=2
    const float sP  = sqrtf(P);
    const float rsP = 1.0f / sP;
    const float C00 = C00p[0];

    // ---- build weight table: 6 pre-splatted rows per tap ----
    for (int j = t; j < NT3; j += TILE) {
        float wrP1 = (j <= 200) ? fwm_wr[2 * NTAPS + j] : 0.f;
        float wiP1 = (j <= 200) ? fwm_wi[2 * NTAPS + j] : 0.f;
        float wrP2 = (j <= 200) ? fwm_wr[3 * NTAPS + j] : 0.f;
        float wiP2 = (j <= 200) ? fwm_wi[3 * NTAPS + j] : 0.f;
        float wrM1 = (j >= 1 && j <= 201) ? fwm_wr[1 * NTAPS + (j - 1)] : 0.f;
        float wiM1 = (j >= 1 && j <= 201) ? fwm_wi[1 * NTAPS + (j - 1)] : 0.f;
        float wrM2 = (j >= 2 && j <= 202) ? fwm_wr[0 * NTAPS + (j - 2)] : 0.f;
        float wiM2 = (j >= 2 && j <= 202) ? fwm_wi[0 * NTAPS + (j - 2)] : 0.f;
        float wx   = (j <= 200) ? ixpm_w[j]   : 0.f;
        float wq   = (j <= 200) ? icixpm_w[j] : 0.f;
        sW6[6 * j + 0] = make_ulonglong2(pk(wrP1, wrP1), pk(wiP1, wiP1));
        sW6[6 * j + 1] = make_ulonglong2(pk(wrP2, wrP2), pk(wiP2, wiP2));
        sW6[6 * j + 2] = make_ulonglong2(pk(wrM1, wrM1), pk(wiM1, wiM1));
        sW6[6 * j + 3] = make_ulonglong2(pk(wrM2, wrM2), pk(wiM2, wiM2));
        sW6[6 * j + 4] = make_ulonglong2(pk(wq, wq), pk(wq, wq));   // side0 scalar
        sW6[6 * j + 5] = make_ulonglong2(pk(wx, wx), pk(wx, wx));   // side1 scalar
    }

    // ---- load scaled x window with mod-M wrap ----
    const float* xr = x_real + (size_t)b * M * 2;
    const float* xi = x_imag + (size_t)b * M * 2;
    for (int idx = t; idx < WIN; idx += TILE) {
        int g  = l0 - 2 + idx;
        int gm = (g < 0) ? g + M : ((g >= M) ? g - M : g);
        float r0 = xr[gm * 2 + 0] * sP, r1 = xr[gm * 2 + 1] * sP;
        float i0 = xi[gm * 2 + 0] * sP, i1 = xi[gm * 2 + 1] * sP;
        sU[idx] = make_ulonglong2(pk(r0, i0), pk(r1, i1));
    }
    __syncthreads();

    // ---- phase 1: per-position products into parity-split arrays ----
    for (int idx = t; idx < 330; idx += TILE) {
        int p = idx + 2;
        ulonglong2 u0 = sU[p], u1 = sU[p - 1], u2 = sU[p - 2];
        float2 f0 = upk(u0.x), f1 = upk(u0.y);
        float2 a0 = upk(u1.x), a1 = upk(u1.y);
        float2 b0 = upk(u2.x), b1 = upk(u2.y);
        int po = (p & 1) * 5;
        int ix = p >> 1;
        sD[(po + 0) * STP + ix] = make_ulonglong2(
            pk(f0.x * a0.x + f0.y * a0.y, f0.y * a0.x - f0.x * a0.y),
            pk(f0.x * a1.x + f0.y * a1.y, f0.y * a1.x - f0.x * a1.y));
        sD[(po + 1) * STP + ix] = make_ulonglong2(
            pk(f1.x * a0.x + f1.y * a0.y, f1.y * a0.x - f1.x * a0.y),
            pk(f1.x * a1.x + f1.y * a1.y, f1.y * a1.x - f1.x * a1.y));
        sD[(po + 2) * STP + ix] = make_ulonglong2(
            pk(f0.x * b0.x + f0.y * b0.y, f0.y * b0.x - f0.x * b0.y),
            pk(f0.x * b1.x + f0.y * b1.y, f0.y * b1.x - f0.x * b1.y));
        sD[(po + 3) * STP + ix] = make_ulonglong2(
            pk(f1.x * b0.x + f1.y * b0.y, f1.y * b0.x - f1.x * b0.y),
            pk(f1.x * b1.x + f1.y * b1.y, f1.y * b1.x - f1.x * b1.y));
        float p0 = f0.x * f0.x + f0.y * f0.y;
        float p1 = f1.x * f1.x + f1.y * f1.y;
        sD[(po + 4) * STP + ix] = make_ulonglong2(
            pk(f0.x * f1.x + f0.y * f1.y, f0.y * f1.x - f0.x * f1.y),
            pk(2.f * p0 + p1, 2.f * p1 + p0));
    }
    __syncthreads();

    const int q = t >> 1;          // output pair id
    const int s = t & 1;           // side: 0 -> +/-1 filters+icixpm, 1 -> +/-2+ixpm
    const int base = 2 * q;
    const int lA = l0 + base;

    // ---- per-side accumulators for BOTH outputs ----
    ull GpA[4], GqA[4], GmA[4], GnA[4];
    ull GpB[4], GqB[4], GmB[4], GnB[4];
#pragma unroll
    for (int k = 0; k < 4; ++k) {
        GpA[k] = GqA[k] = GmA[k] = GnA[k] = 0ULL;
        GpB[k] = GqB[k] = GmB[k] = GnB[k] = 0ULL;
    }
    ull scA = 0ULL, scB = 0ULL;    // side0: (qcr,qci); side1: (axp0,axp1)

    const ulonglong2* dP0 = sD + (2 * s) * STP;          // even-tap products
    const ulonglong2* dP1 = sD + (2 * s + 1) * STP;
    const ulonglong2* dO0 = sD + (5 + 2 * s) * STP;      // odd-tap products
    const ulonglong2* dO1 = sD + (5 + 2 * s + 1) * STP;
    const ull* scE = (const ull*)(sD + 4 * STP);         // {q, ps} even taps
    const ull* scO = (const ull*)(sD + 9 * STP);         // odd taps

    ulonglong2 z2 = make_ulonglong2(0ULL, 0ULL);
    ulonglong2 pP = z2, pM = z2;   // previous tap's weights (for output B)
    ull pS = 0ULL;

#pragma unroll 2
    for (int k = 0; k < NT3 / 2; ++k) {
        const int ix = q + 1 + k;
        // even tap j = 2k
        ulonglong2 e0 = dP0[ix];
        ulonglong2 e1 = dP1[ix];
        ull ssc = scE[2 * ix + s];
        ulonglong2 wP = sW6[12 * k + s];
        ulonglong2 wM = sW6[12 * k + 2 + s];
        ull wS = *(const ull*)&sW6[12 * k + 4 + s];
        ACC(e0, e1, ssc, wP, wM, wS, pP, pM, pS);

        // odd tap j = 2k+1 (output B uses even tap's weights)
        ulonglong2 o0 = dO0[ix];
        ulonglong2 o1 = dO1[ix];
        ull osc = scO[2 * ix + s];
        ulonglong2 vP = sW6[12 * k + 6 + s];
        ulonglong2 vM = sW6[12 * k + 8 + s];
        ull vS = *(const ull*)&sW6[12 * k + 10 + s];
        ACC(o0, o1, osc, vP, vM, vS, wP, wM, wS);

        pP = vP; pM = vM; pS = vS;
    }

    const float wxc = ixpm_w[HALF];
    const float wqc = icixpm_w[HALF];
    const int sw[4] = {0, 2, 1, 3};

    float ov[8];   // partial outputs: [0..3] = output A (o0r,o0i,o1r,o1i), [4..7] = B

#pragma unroll
    for (int oo = 0; oo < 2; ++oo) {
        const ull* Gp = oo ? GpB : GpA;
        const ull* Gq = oo ? GqB : GqA;
        const ull* Gm = oo ? GmB : GmA;
        const ull* Gn = oo ? GnB : GnA;
        float2 scf = upk(oo ? scB : scA);
        const int bi = base + oo;

        // center position
        ulonglong2 xcu = sU[bi + 102];
        float2 x0 = upk(xcu.x), x1 = upk(xcu.y);
        float xc_x = x0.x, xc_y = x0.y, xc_z = x1.x, xc_w = x1.y;

        // recombine G for this side's two filters
        float Pr[4], Pi[4], Mr[4], Mi[4];
#pragma unroll
        for (int m = 0; m < 4; ++m) {
            float2 a = upk(Gp[m]), bb = upk(Gq[m]);
            Pr[m] = a.x - bb.y;  Pi[m] = a.y + bb.x;
            a = upk(Gm[sw[m]]);  bb = upk(Gn[sw[m]]);
            Mr[m] = a.x + bb.y;  Mi[m] = bb.x - a.y;
        }

        // fwm partial: plus shift (s+1): xs at bi+101-s ; minus: bi+103+s
        float f0r = 0.f, f0i = 0.f, f1r = 0.f, f1i = 0.f;
        {
            ulonglong2 xsu = sU[bi + 101 - s];
            float2 s0f = upk(xsu.x), s1f = upk(xsu.y);
            float fA0r = 2.f * Pr[0] + Pr[3], fA0i = 2.f * Pi[0] + Pi[3];
            float fA1r = 2.f * Pr[3] + Pr[0], fA1i = 2.f * Pi[3] + Pi[0];
            f0r += s0f.x * fA0r - s0f.y * fA0i;
            f0i += s0f.x * fA0i + s0f.y * fA0r;
            f0r += s1f.x * Pr[1] - s1f.y * Pi[1];
            f0i += s1f.x * Pi[1] + s1f.y * Pr[1];
            f1r += s1f.x * fA1r - s1f.y * fA1i;
            f1i += s1f.x * fA1i + s1f.y * fA1r;
            f1r += s0f.x * Pr[2] - s0f.y * Pi[2];
            f1i += s0f.x * Pi[2] + s0f.y * Pr[2];
        }
        {
            ulonglong2 xsu = sU[bi + 103 + s];
            float2 s0f = upk(xsu.x), s1f = upk(xsu.y);
            float fA0r = 2.f * Mr[0] + Mr[3], fA0i = 2.f * Mi[0] + Mi[3];
            float fA1r = 2.f * Mr[3] + Mr[0], fA1i = 2.f * Mi[3] + Mi[0];
            f0r += s0f.x * fA0r - s0f.y * fA0i;
            f0i += s0f.x * fA0i + s0f.y * fA0r;
            f0r += s1f.x * Mr[1] - s1f.y * Mi[1];
            f0i += s1f.x * Mi[1] + s1f.y * Mr[1];
            f1r += s1f.x * fA1r - s1f.y * fA1i;
            f1i += s1f.x * fA1i + s1f.y * fA1r;
            f1r += s0f.x * Mr[2] - s0f.y * Mi[2];
            f1i += s0f.x * Mi[2] + s0f.y * Mr[2];
        }

        float pc0 = xc_x * xc_x + xc_y * xc_y;
        float pc1 = xc_z * xc_z + xc_w * xc_w;

        if (s == 0) {
            // icixpm: correct qc, add ici
            float qcr = scf.x - wqc * (xc_x * xc_z + xc_y * xc_w);
            float qci = scf.y - wqc * (xc_y * xc_z - xc_x * xc_w);
            f0r += -(xc_z * qci + xc_w * qcr);
            f0i +=   xc_z * qcr - xc_w * qci;
            f1r +=   xc_x * qci - xc_y * qcr;
            f1i +=   xc_x * qcr + xc_y * qci;
        } else {
            // ixpm: correct axp, phase rotate center sample
            float axp0 = scf.x - wxc * (2.f * pc0 + pc1);
            float axp1 = scf.y - wxc * (2.f * pc1 + pc0);
            float spm  = C00 * (pc0 + pc1);
            float phi0 = spm + 2.f * axp0;
            float phi1 = spm + 2.f * axp1;
            float s0, c0, s1, c1;
            sincosf(phi0, &s0, &c0);
            sincosf(phi1, &s1, &c1);
            f0r += xc_x * c0 - xc_y * s0;
            f0i += xc_x * s0 + xc_y * c0;
            f1r += xc_z * c1 - xc_w * s1;
            f1i += xc_z * s1 + xc_w * c1;
        }

        ov[4 * oo + 0] = f0r;
        ov[4 * oo + 1] = f0i;
        ov[4 * oo + 2] = f1r;
        ov[4 * oo + 3] = f1i;
    }

    // exchange partials with pair partner (full warp active)
#pragma unroll
    for (int i = 0; i < 8; ++i)
        ov[i] += __shfl_xor_sync(0xffffffffu, ov[i], 1);

    const int l = lA + s;          // side s stores output lA+s (coalesced)
    if (l < Lout) {
        const float* m = ov + 4 * s;
        float4* outv = (float4*)(out + ((size_t)(b * (size_t)Lout + l)) * 4);
        *outv = make_float4(m[0] * rsP, m[1] * rsP, m[2] * rsP, m[3] * rsP);
    }
}

extern "C" void kernel_launch(void* const* d_in, const int* in_sizes, int n_in,
                              void* d_out, int out_size)
{
    const float* x_real    = (const float*)d_in[0];
    const float* x_imag    = (const float*)d_in[1];
    const float* task_info = (const float*)d_in[2];
    const float* C00       = (const float*)d_in[3];
    const float* ixpm_w    = (const float*)d_in[4];
    const float* icixpm_w  = (const float*)d_in[5];
    const float* fwm_wr    = (const float*)d_in[6];
    const float* fwm_wi    = (const float*)d_in[7];

    int B = in_sizes[2] / 4;
    int M = in_sizes[0] / (B * 2);
    int Lout = M - NTAPS + 1;

    cudaFuncSetAttribute(snse_kernel,
                         cudaFuncAttributeMaxDynamicSharedMemorySize, DYNBYTES);

    dim3 grid((Lout + OUTS - 1) / OUTS, B);
    snse_kernel<<<grid, TILE, DYNBYTES>>>(x_real, x_imag, task_info, C00,
                                          ixpm_w, icixpm_w, fwm_wr, fwm_wi,
                                          (float*)d_out, M, Lout);
}

// round 13
// speedup vs baseline: 2.2164x; 1.3193x over previous
#include <cuda_runtime.h>
#include <math.h>

#define NTAPS 201
#define HALF  100
#define NT3   204           // taps 0..202 used + zero row 203; 204 = 2*102
#define TILE  128           // threads; each thread computes 2 adjacent outputs
#define OUTS  256           // outputs per block
#define WIN   464           // window entries (need 461)
#define STP   233           // per-array stride (ulonglong2 units), odd to de-conflict
#define DYNBYTES (10 * STP * 16)
#define NW    (NT3 * 10)    // weight table: 10 ull per tap

typedef unsigned long long ull;

// Weight table in CONSTANT memory: warp-uniform accesses compile to LDCU into
// uniform registers, so the accumulate FFMA2s carry only 2 distinct vector-RF
// 64-bit operands (acc, product) -> RF-bank rt drops 3 -> 2 (1.5x fma rate).
__constant__ ull cW[NW];
__device__ ull gWstage[NW];

__device__ __forceinline__ ull pk(float lo, float hi) {
    ull r; asm("mov.b64 %0, {%1, %2};" : "=l"(r) : "f"(lo), "f"(hi)); return r;
}
__device__ __forceinline__ float2 upk(ull v) {
    float2 r; asm("mov.b64 {%0, %1}, %2;" : "=f"(r.x), "=f"(r.y) : "l"(v)); return r;
}
__device__ __forceinline__ void fma2(ull &d, ull a, ull b) {
    asm("fma.rn.f32x2 %0, %1, %2, %0;" : "+l"(d) : "l"(a), "l"(b));
}

// Per tap j, 10 ull rows in cW (same content as R10's shared table):
//   [10j+0,1] = w(+1) splats {(wr,wr),(wi,wi)}   [10j+2,3] = w(+2)
//   [10j+4,5] = w(-1) (tap-shifted)              [10j+6,7] = w(-2)
//   [10j+8]   = (wx,wx) ixpm                     [10j+9]   = (wq,wq) icixpm
__global__ void prep_weights(const float* __restrict__ ixpm_w,
                             const float* __restrict__ icixpm_w,
                             const float* __restrict__ fwm_wr,
                             const float* __restrict__ fwm_wi)
{
    int j = blockIdx.x * blockDim.x + threadIdx.x;
    if (j >= NT3) return;
    float wrP1 = (j <= 200) ? fwm_wr[2 * NTAPS + j] : 0.f;
    float wiP1 = (j <= 200) ? fwm_wi[2 * NTAPS + j] : 0.f;
    float wrP2 = (j <= 200) ? fwm_wr[3 * NTAPS + j] : 0.f;
    float wiP2 = (j <= 200) ? fwm_wi[3 * NTAPS + j] : 0.f;
    float wrM1 = (j >= 1 && j <= 201) ? fwm_wr[1 * NTAPS + (j - 1)] : 0.f;
    float wiM1 = (j >= 1 && j <= 201) ? fwm_wi[1 * NTAPS + (j - 1)] : 0.f;
    float wrM2 = (j >= 2 && j <= 202) ? fwm_wr[0 * NTAPS + (j - 2)] : 0.f;
    float wiM2 = (j >= 2 && j <= 202) ? fwm_wi[0 * NTAPS + (j - 2)] : 0.f;
    float wx   = (j <= 200) ? ixpm_w[j]   : 0.f;
    float wq   = (j <= 200) ? icixpm_w[j] : 0.f;
    gWstage[10 * j + 0] = pk(wrP1, wrP1);
    gWstage[10 * j + 1] = pk(wiP1, wiP1);
    gWstage[10 * j + 2] = pk(wrP2, wrP2);
    gWstage[10 * j + 3] = pk(wiP2, wiP2);
    gWstage[10 * j + 4] = pk(wrM1, wrM1);
    gWstage[10 * j + 5] = pk(wiM1, wiM1);
    gWstage[10 * j + 6] = pk(wrM2, wrM2);
    gWstage[10 * j + 7] = pk(wiM2, wiM2);
    gWstage[10 * j + 8] = pk(wx, wx);
    gWstage[10 * j + 9] = pk(wq, wq);
}

// accumulate one tap: products E0..E4, current weights W* (output A),
// previous-tap weights P* (output B). Weight args are plain ulls (UR-eligible).
#define ACC_TAP(E0,E1,E2,E3,E4, WA0,WA1,WB0,WB1,WC0,WC1,WD0,WD1,WE0,WE1,      \
                PA0,PA1,PB0,PB1,PC0,PC1,PD0,PD1,PE0,PE1) do {                 \
    ull d0=(E0).x, d1=(E0).y, d2=(E1).x, d3=(E1).y;                           \
    ull d4=(E2).x, d5=(E2).y, d6=(E3).x, d7=(E3).y;                           \
    ull qd=(E4).x, ps=(E4).y;                                                 \
    fma2(axpA, ps, (WE0));  fma2(axpB, ps, (PE0));                            \
    fma2(qcA,  qd, (WE1));  fma2(qcB,  qd, (PE1));                            \
    fma2(ApA[0], d0, (WA0)); fma2(BpA[0], d0, (WA1));                         \
    fma2(AmA[0], d0, (WC0)); fma2(BmA[0], d0, (WC1));                         \
    fma2(ApB[0], d0, (PA0)); fma2(BpB[0], d0, (PA1));                         \
    fma2(AmB[0], d0, (PC0)); fma2(BmB[0], d0, (PC1));                         \
    fma2(ApA[1], d1, (WA0)); fma2(BpA[1], d1, (WA1));                         \
    fma2(AmA[1], d1, (WC0)); fma2(BmA[1], d1, (WC1));                         \
    fma2(ApB[1], d1, (PA0)); fma2(BpB[1], d1, (PA1));                         \
    fma2(AmB[1], d1, (PC0)); fma2(BmB[1], d1, (PC1));                         \
    fma2(ApA[2], d2, (WA0)); fma2(BpA[2], d2, (WA1));                         \
    fma2(AmA[2], d2, (WC0)); fma2(BmA[2], d2, (WC1));                         \
    fma2(ApB[2], d2, (PA0)); fma2(BpB[2], d2, (PA1));                         \
    fma2(AmB[2], d2, (PC0)); fma2(BmB[2], d2, (PC1));                         \
    fma2(ApA[3], d3, (WA0)); fma2(BpA[3], d3, (WA1));                         \
    fma2(AmA[3], d3, (WC0)); fma2(BmA[3], d3, (WC1));                         \
    fma2(ApB[3], d3, (PA0)); fma2(BpB[3], d3, (PA1));                         \
    fma2(AmB[3], d3, (PC0)); fma2(BmB[3], d3, (PC1));                         \
    fma2(ApA[4], d4, (WB0)); fma2(BpA[4], d4, (WB1));                         \
    fma2(AmA[4], d4, (WD0)); fma2(BmA[4], d4, (WD1));                         \
    fma2(ApB[4], d4, (PB0)); fma2(BpB[4], d4, (PB1));                         \
    fma2(AmB[4], d4, (PD0)); fma2(BmB[4], d4, (PD1));                         \
    fma2(ApA[5], d5, (WB0)); fma2(BpA[5], d5, (WB1));                         \
    fma2(AmA[5], d5, (WD0)); fma2(BmA[5], d5, (WD1));                         \
    fma2(ApB[5], d5, (PB0)); fma2(BpB[5], d5, (PB1));                         \
    fma2(AmB[5], d5, (PD0)); fma2(BmB[5], d5, (PD1));                         \
    fma2(ApA[6], d6, (WB0)); fma2(BpA[6], d6, (WB1));                         \
    fma2(AmA[6], d6, (WD0)); fma2(BmA[6], d6, (WD1));                         \
    fma2(ApB[6], d6, (PB0)); fma2(BpB[6], d6, (PB1));                         \
    fma2(AmB[6], d6, (PD0)); fma2(BmB[6], d6, (PD1));                         \
    fma2(ApA[7], d7, (WB0)); fma2(BpA[7], d7, (WB1));                         \
    fma2(AmA[7], d7, (WD0)); fma2(BmA[7], d7, (WD1));                         \
    fma2(ApB[7], d7, (PB0)); fma2(BpB[7], d7, (PB1));                         \
    fma2(AmB[7], d7, (PD0)); fma2(BmB[7], d7, (PD1));                         \
} while (0)

__global__ __launch_bounds__(TILE, 2)
void snse_kernel(const float* __restrict__ x_real,
                 const float* __restrict__ x_imag,
                 const float* __restrict__ task_info,
                 const float* __restrict__ C00p,
                 const float* __restrict__ ixpm_w,
                 const float* __restrict__ icixpm_w,
                 float* __restrict__ out,
                 int M, int Lout)
{
    __shared__ ulonglong2 sU[WIN];
    extern __shared__ ulonglong2 sD[];     // 10 arrays of STP ulonglong2

    const int b  = blockIdx.y;
    const int l0 = blockIdx.x * OUTS;
    const int t  = threadIdx.x;

    const float dbm = task_info[b * 4];
    const float P   = exp10f(dbm * 0.1f) * 0.5f;   // /Nm, Nm=2
    const float sP  = sqrtf(P);
    const float rsP = 1.0f / sP;
    const float C00 = C00p[0];

    // ---- load scaled x window with mod-M wrap ----
    const float* xr = x_real + (size_t)b * M * 2;
    const float* xi = x_imag + (size_t)b * M * 2;
    for (int idx = t; idx < WIN; idx += TILE) {
        int g  = l0 - 2 + idx;
        int gm = (g < 0) ? g + M : ((g >= M) ? g - M : g);
        float r0 = xr[gm * 2 + 0] * sP, r1 = xr[gm * 2 + 1] * sP;
        float i0 = xi[gm * 2 + 0] * sP, i1 = xi[gm * 2 + 1] * sP;
        sU[idx] = make_ulonglong2(pk(r0, i0), pk(r1, i1));
    }
    __syncthreads();

    // ---- phase 1: per-position products into parity-split arrays ----
    // arrays 0..4 even p / 5..9 odd p, index p>>1 (R10 layout)
    for (int idx = t; idx < 459; idx += TILE) {
        int p = idx + 2;
        ulonglong2 u0 = sU[p], u1 = sU[p - 1], u2 = sU[p - 2];
        float2 f0 = upk(u0.x), f1 = upk(u0.y);
        float2 a0 = upk(u1.x), a1 = upk(u1.y);
        float2 b0 = upk(u2.x), b1 = upk(u2.y);
        int po = (p & 1) * 5;
        int ix = p >> 1;
        sD[(po + 0) * STP + ix] = make_ulonglong2(
            pk(f0.x * a0.x + f0.y * a0.y, f0.y * a0.x - f0.x * a0.y),
            pk(f0.x * a1.x + f0.y * a1.y, f0.y * a1.x - f0.x * a1.y));
        sD[(po + 1) * STP + ix] = make_ulonglong2(
            pk(f1.x * a0.x + f1.y * a0.y, f1.y * a0.x - f1.x * a0.y),
            pk(f1.x * a1.x + f1.y * a1.y, f1.y * a1.x - f1.x * a1.y));
        sD[(po + 2) * STP + ix] = make_ulonglong2(
            pk(f0.x * b0.x + f0.y * b0.y, f0.y * b0.x - f0.x * b0.y),
            pk(f0.x * b1.x + f0.y * b1.y, f0.y * b1.x - f0.x * b1.y));
        sD[(po + 3) * STP + ix] = make_ulonglong2(
            pk(f1.x * b0.x + f1.y * b0.y, f1.y * b0.x - f1.x * b0.y),
            pk(f1.x * b1.x + f1.y * b1.y, f1.y * b1.x - f1.x * b1.y));
        float p0 = f0.x * f0.x + f0.y * f0.y;
        float p1 = f1.x * f1.x + f1.y * f1.y;
        sD[(po + 4) * STP + ix] = make_ulonglong2(
            pk(f0.x * f1.x + f0.y * f1.y, f0.y * f1.x - f0.x * f1.y),
            pk(2.f * p0 + p1, 2.f * p1 + p0));
    }
    __syncthreads();

    const int base = 2 * t;
    const int lA = l0 + base;

    // ---- accumulators for BOTH outputs ----
    ull ApA[8], BpA[8], AmA[8], BmA[8];
    ull ApB[8], BpB[8], AmB[8], BmB[8];
#pragma unroll
    for (int k = 0; k < 8; ++k) {
        ApA[k] = BpA[k] = AmA[k] = BmA[k] = 0ULL;
        ApB[k] = BpB[k] = AmB[k] = BmB[k] = 0ULL;
    }
    ull axpA = 0ULL, axpB = 0ULL;
    ull qcA  = 0ULL, qcB  = 0ULL;

    // previous-tap weights (for output B); zero before tap 0
    ull pA0 = 0, pA1 = 0, pB0 = 0, pB1 = 0, pC0 = 0, pC1 = 0;
    ull pD0 = 0, pD1 = 0, pE0 = 0, pE1 = 0;

    // taps in parity pairs; products at consecutive lane indices (coalesced)
#pragma unroll 2
    for (int k = 0; k < NT3 / 2; ++k) {
        const int ix = t + 1 + k;
        // even tap j = 2k : weights cW[20k + 0..9]
        ulonglong2 e0 = sD[0 * STP + ix];
        ulonglong2 e1 = sD[1 * STP + ix];
        ulonglong2 e2 = sD[2 * STP + ix];
        ulonglong2 e3 = sD[3 * STP + ix];
        ulonglong2 e4 = sD[4 * STP + ix];
        ull wA0 = cW[20 * k + 0], wA1 = cW[20 * k + 1];
        ull wB0 = cW[20 * k + 2], wB1 = cW[20 * k + 3];
        ull wC0 = cW[20 * k + 4], wC1 = cW[20 * k + 5];
        ull wD0 = cW[20 * k + 6], wD1 = cW[20 * k + 7];
        ull wE0 = cW[20 * k + 8], wE1 = cW[20 * k + 9];
        ACC_TAP(e0, e1, e2, e3, e4,
                wA0, wA1, wB0, wB1, wC0, wC1, wD0, wD1, wE0, wE1,
                pA0, pA1, pB0, pB1, pC0, pC1, pD0, pD1, pE0, pE1);

        // odd tap j = 2k+1 : weights cW[20k + 10..19]; B side uses even tap's
        ulonglong2 o0 = sD[5 * STP + ix];
        ulonglong2 o1 = sD[6 * STP + ix];
        ulonglong2 o2 = sD[7 * STP + ix];
        ulonglong2 o3 = sD[8 * STP + ix];
        ulonglong2 o4 = sD[9 * STP + ix];
        ull vA0 = cW[20 * k + 10], vA1 = cW[20 * k + 11];
        ull vB0 = cW[20 * k + 12], vB1 = cW[20 * k + 13];
        ull vC0 = cW[20 * k + 14], vC1 = cW[20 * k + 15];
        ull vD0 = cW[20 * k + 16], vD1 = cW[20 * k + 17];
        ull vE0 = cW[20 * k + 18], vE1 = cW[20 * k + 19];
        ACC_TAP(o0, o1, o2, o3, o4,
                vA0, vA1, vB0, vB1, vC0, vC1, vD0, vD1, vE0, vE1,
                wA0, wA1, wB0, wB1, wC0, wC1, wD0, wD1, wE0, wE1);

        pA0 = vA0; pA1 = vA1; pB0 = vB0; pB1 = vB1; pC0 = vC0; pC1 = vC1;
        pD0 = vD0; pD1 = vD1; pE0 = vE0; pE1 = vE1;
    }

    const float wxc = ixpm_w[HALF];
    const float wqc = icixpm_w[HALF];

#pragma unroll
    for (int o = 0; o < 2; ++o) {
        const int l = lA + o;
        if (l >= Lout) break;
        const int bi = base + o;
        const ull* Ap = o ? ApB : ApA;
        const ull* Bp = o ? BpB : BpA;
        const ull* Am = o ? AmB : AmA;
        const ull* Bm = o ? BmB : BmA;
        float2 axpf = upk(o ? axpB : axpA);
        float2 qcf  = upk(o ? qcB  : qcA);
        float axp0 = axpf.x, axp1 = axpf.y;
        float qcr = qcf.x, qci = qcf.y;

        ulonglong2 xcu = sU[bi + 102];
        float2 x0 = upk(xcu.x), x1 = upk(xcu.y);
        float xc_x = x0.x, xc_y = x0.y, xc_z = x1.x, xc_w = x1.y;

        float pc0 = xc_x * xc_x + xc_y * xc_y;
        float pc1 = xc_z * xc_z + xc_w * xc_w;
        axp0 -= wxc * (2.f * pc0 + pc1);
        axp1 -= wxc * (2.f * pc1 + pc0);
        qcr -= wqc * (xc_x * xc_z + xc_y * xc_w);
        qci -= wqc * (xc_y * xc_z - xc_x * xc_w);

        float spm  = C00 * (pc0 + pc1);
        float phi0 = spm + 2.f * axp0;
        float phi1 = spm + 2.f * axp1;

        float ici0r = -(xc_z * qci + xc_w * qcr);
        float ici0i =   xc_z * qcr - xc_w * qci;
        float ici1r =   xc_x * qci - xc_y * qcr;
        float ici1i =   xc_x * qcr + xc_y * qci;

        float Gr[4][4], Gi[4][4];
        const int sw[4] = {0, 2, 1, 3};
#pragma unroll
        for (int m = 0; m < 4; ++m) {
            float2 a, bb;
            a = upk(Ap[m]); bb = upk(Bp[m]);
            Gr[2][m] = a.x - bb.y;  Gi[2][m] = a.y + bb.x;
            a = upk(Ap[4 + m]); bb = upk(Bp[4 + m]);
            Gr[3][m] = a.x - bb.y;  Gi[3][m] = a.y + bb.x;
            a = upk(Am[sw[m]]); bb = upk(Bm[sw[m]]);
            Gr[1][m] = a.x + bb.y;  Gi[1][m] = bb.x - a.y;
            a = upk(Am[4 + sw[m]]); bb = upk(Bm[4 + sw[m]]);
            Gr[0][m] = a.x + bb.y;  Gi[0][m] = bb.x - a.y;
        }

        float fwm0r = 0.f, fwm0i = 0.f, fwm1r = 0.f, fwm1i = 0.f;
        const int soff[4] = {104, 103, 101, 100};
#pragma unroll
        for (int k = 0; k < 4; ++k) {
            ulonglong2 xsu = sU[bi + soff[k]];
            float2 s0f = upk(xsu.x), s1f = upk(xsu.y);
            float xs_x = s0f.x, xs_y = s0f.y, xs_z = s1f.x, xs_w = s1f.y;
            float G00r = Gr[k][0], G00i = Gi[k][0];
            float G01r = Gr[k][1], G01i = Gi[k][1];
            float G10r = Gr[k][2], G10i = Gi[k][2];
            float G11r = Gr[k][3], G11i = Gi[k][3];
            float fA0r = 2.f * G00r + G11r, fA0i = 2.f * G00i + G11i;
            float fA1r = 2.f * G11r + G00r, fA1i = 2.f * G11i + G00i;
            fwm0r += xs_x * fA0r - xs_y * fA0i;
            fwm0i += xs_x * fA0i + xs_y * fA0r;
            fwm0r += xs_z * G01r - xs_w * G01i;
            fwm0i += xs_z * G01i + xs_w * G01r;
            fwm1r += xs_z * fA1r - xs_w * fA1i;
            fwm1i += xs_z * fA1i + xs_w * fA1r;
            fwm1r += xs_x * G10r - xs_y * G10i;
            fwm1i += xs_x * G10i + xs_y * G10r;
        }

        float s0, c0, s1, c1;
        sincosf(phi0, &s0, &c0);
        sincosf(phi1, &s1, &c1);
        float o0r = xc_x * c0 - xc_y * s0 + ici0r + fwm0r;
        float o0i = xc_x * s0 + xc_y * c0 + ici0i + fwm0i;
        float o1r = xc_z * c1 - xc_w * s1 + ici1r + fwm1r;
        float o1i = xc_z * s1 + xc_w * c1 + ici1i + fwm1i;

        float4* outv = (float4*)(out + ((size_t)(b * (size_t)Lout + l)) * 4);
        *outv = make_float4(o0r * rsP, o0i * rsP, o1r * rsP, o1i * rsP);
    }
}

extern "C" void kernel_launch(void* const* d_in, const int* in_sizes, int n_in,
                              void* d_out, int out_size)
{
    const float* x_real    = (const float*)d_in[0];
    const float* x_imag    = (const float*)d_in[1];
    const float* task_info = (const float*)d_in[2];
    const float* C00       = (const float*)d_in[3];
    const float* ixpm_w    = (const float*)d_in[4];
    const float* icixpm_w  = (const float*)d_in[5];
    const float* fwm_wr    = (const float*)d_in[6];
    const float* fwm_wi    = (const float*)d_in[7];

    int B = in_sizes[2] / 4;
    int M = in_sizes[0] / (B * 2);
    int Lout = M - NTAPS + 1;

    // build weight table -> staging buffer -> constant bank.
    // NOTE (R12 bug): __device__/__constant__ symbols must be resolved to
    // device addresses via cudaGetSymbolAddress before any memcpy; passing
    // the symbol as a raw pointer silently copies garbage.
    prep_weights<<<(NT3 + 255) / 256, 256>>>(ixpm_w, icixpm_w, fwm_wr, fwm_wi);
    void* srcAddr = nullptr;
    void* dstAddr = nullptr;
    cudaGetSymbolAddress(&srcAddr, gWstage);
    cudaGetSymbolAddress(&dstAddr, cW);
    cudaMemcpyAsync(dstAddr, srcAddr, NW * sizeof(ull),
                    cudaMemcpyDeviceToDevice, 0);

    cudaFuncSetAttribute(snse_kernel,
                         cudaFuncAttributeMaxDynamicSharedMemorySize, DYNBYTES);

    dim3 grid((Lout + OUTS - 1) / OUTS, B);
    snse_kernel<<<grid, TILE, DYNBYTES>>>(x_real, x_imag, task_info, C00,
                                          ixpm_w, icixpm_w,
                                          (float*)d_out, M, Lout);
}